// round 13
// baseline (speedup 1.0000x reference)
#include <cuda_runtime.h>
#include <cuda_fp16.h>
#include <cstdint>

#define TOK   8192
#define DDIM  1024
#define FDIM  4096
#define NEXP  8
#define CAST_N4 (NEXP * DDIM * FDIM / 4)   // 8.39M float4 per weight tensor
#define OUT_N4  (TOK * DDIM / 4)           // 2.1M float4 of output to zero

// ---------------- device scratch ----------------
__device__ __half g_xh[(size_t)TOK * DDIM];             // fp16 inputs
__device__ __half g_h[(size_t)NEXP * 8192 * FDIM];      // fp16 silu(x@W1+b1)
__device__ __half g_w1h[(size_t)NEXP * DDIM * FDIM];    // W1 fp16, [K][N] layout
__device__ __half g_w2h[(size_t)NEXP * DDIM * FDIM];    // W2 fp16, [K][N] layout
__device__ int    g_tok[NEXP * 8192];
__device__ float  g_w[NEXP * 8192];
__device__ float  g_partial[1024 * NEXP];
__device__ int    g_cnt[NEXP];

// ---------------- helpers ----------------
__device__ __forceinline__ uint32_t smem_to_u32(const void* p) {
    uint32_t a;
    asm("{ .reg .u64 t; cvta.to.shared.u64 t, %1; cvt.u32.u64 %0, t; }" : "=r"(a) : "l"(p));
    return a;
}
__device__ __forceinline__ void cp16(uint32_t dst, const void* src) {
    asm volatile("cp.async.cg.shared.global [%0], [%1], 16;" :: "r"(dst), "l"(src));
}
// arrive on mbarrier when this thread's prior cp.asyncs complete (.noinc: counts
// against the init count — one tracked arrive per thread).
#define CP_MBAR_ARRIVE(mbar) \
    asm volatile("cp.async.mbarrier.arrive.noinc.shared.b64 [%0];" :: "r"((uint32_t)(mbar)) : "memory")

#define MBARRIER_INIT(mbar, count) \
    asm volatile("mbarrier.init.shared.b64 [%0], %1;" \
        :: "r"((uint32_t)(mbar)), "r"((uint32_t)(count)) : "memory")
#define MBARRIER_ARRIVE(mbar) \
    asm volatile("mbarrier.arrive.shared.b64 _, [%0];" :: "r"((uint32_t)(mbar)) : "memory")

#define MBARRIER_WAIT_PARITY(mbar_smem_addr, phase_parity) do { \
    uint32_t _mbar = (uint32_t)(mbar_smem_addr); \
    uint32_t _parity = (uint32_t)(phase_parity); \
    uint32_t _done; \
    asm volatile("{\n\t.reg .pred p;\n\t" \
        "mbarrier.try_wait.parity.acquire.cta.shared::cta.b64 p, [%1], %2;\n\t" \
        "selp.b32 %0, 1, 0, p;\n\t}" \
        : "=r"(_done) : "r"(_mbar), "r"(_parity) : "memory"); \
    if (!_done) { \
        asm volatile("{\n\t.reg .pred P1;\n\t" \
            "WAIT_LOOP_%=:\n\t" \
            "mbarrier.try_wait.parity.acquire.cta.shared::cta.b64 P1, [%0], %1, 0x989680;\n\t" \
            "@P1 bra.uni WAIT_DONE_%=;\n\t" \
            "bra.uni WAIT_LOOP_%=;\n\t" \
            "WAIT_DONE_%=:\n\t}" \
            :: "r"(_mbar), "r"(_parity) : "memory"); \
    } \
} while(0)

__device__ __forceinline__ void ldsm4(uint32_t* r, uint32_t addr) {
    asm volatile("ldmatrix.sync.aligned.m8n8.x4.shared.b16 {%0,%1,%2,%3}, [%4];"
                 : "=r"(r[0]), "=r"(r[1]), "=r"(r[2]), "=r"(r[3]) : "r"(addr));
}
__device__ __forceinline__ void ldsm4t(uint32_t* r, uint32_t addr) {
    asm volatile("ldmatrix.sync.aligned.m8n8.x4.trans.shared.b16 {%0,%1,%2,%3}, [%4];"
                 : "=r"(r[0]), "=r"(r[1]), "=r"(r[2]), "=r"(r[3]) : "r"(addr));
}
// fp16 MMA, fp32 accumulate: D(16x8) += A(16x16) * B(16x8)
__device__ __forceinline__ void mma16(float* d, const uint32_t* a, const uint32_t* b) {
    asm("mma.sync.aligned.m16n8k16.row.col.f32.f16.f16.f32 "
        "{%0,%1,%2,%3}, {%4,%5,%6,%7}, {%8,%9}, {%0,%1,%2,%3};"
        : "+f"(d[0]), "+f"(d[1]), "+f"(d[2]), "+f"(d[3])
        : "r"(a[0]), "r"(a[1]), "r"(a[2]), "r"(a[3]), "r"(b[0]), "r"(b[1]));
}

__device__ __forceinline__ void cast4(const float* __restrict__ src,
                                      __half* __restrict__ dst, int i) {
    float4 v = ((const float4*)src)[i];
    __half2 h0 = __floats2half2_rn(v.x, v.y);
    __half2 h1 = __floats2half2_rn(v.z, v.w);
    uint2 u;
    u.x = *(uint32_t*)&h0;
    u.y = *(uint32_t*)&h1;
    ((uint2*)dst)[i] = u;
}

// ---------------- small kernels ----------------
__global__ void k_init() {
    if (threadIdx.x < NEXP) g_cnt[threadIdx.x] = 0;
}

// mega pre-kernel: blocks [0,1024) = gating (task-gate inline);
// blocks [1024, 1024+32768) = W1 cast; blocks [33792, 33792+8192) = zero out.
__global__ void k_pregate(const float* __restrict__ x,
                          const float* __restrict__ Wg,
                          const float* __restrict__ bg,
                          const float* __restrict__ alpha_p,
                          const float* __restrict__ task,
                          const float* __restrict__ Wgt,
                          const float* __restrict__ bgt,
                          const float* __restrict__ W1,
                          __half* __restrict__ w1h,
                          float* __restrict__ out) {
    if (blockIdx.x >= 1024 + 32768) {
        int i = (blockIdx.x - 1024 - 32768) * 256 + threadIdx.x;
        if (i < OUT_N4) ((float4*)out)[i] = make_float4(0.f, 0.f, 0.f, 0.f);
        return;
    }
    if (blockIdx.x >= 1024) {
        int i = (blockIdx.x - 1024) * 256 + threadIdx.x;
        if (i < CAST_N4) cast4(W1, w1h, i);
        return;
    }

    // ---- inline task gate ----
    __shared__ float red[256][8];
    __shared__ float tg[8];
    {
        float p[8];
#pragma unroll
        for (int e = 0; e < 8; e++) p[e] = 0.f;
        for (int d = threadIdx.x; d < DDIM; d += 256) {
            float tv = task[d];
#pragma unroll
            for (int e = 0; e < 8; e++) p[e] += tv * Wgt[d * 8 + e];
        }
#pragma unroll
        for (int e = 0; e < 8; e++) red[threadIdx.x][e] = p[e];
        __syncthreads();
        if (threadIdx.x < 8) {
            float s = bgt[threadIdx.x];
            for (int w = 0; w < 256; w++) s += red[w][threadIdx.x];
            tg[threadIdx.x] = s;
        }
        __syncthreads();
    }

    // ---- per-token gating: one warp per token ----
    int warp = threadIdx.x >> 5, lane = threadIdx.x & 31;
    int t = blockIdx.x * 8 + warp;
    const float* xr = x + (size_t)t * DDIM;
    __half* xw = g_xh + (size_t)t * DDIM;

    float acc[8];
#pragma unroll
    for (int e = 0; e < 8; e++) acc[e] = 0.f;
#pragma unroll 4
    for (int i = 0; i < 32; i++) {
        int d = i * 32 + lane;
        float xv = xr[d];
        xw[d] = __float2half_rn(xv);
#pragma unroll
        for (int e = 0; e < 8; e++) acc[e] += xv * Wg[d * 8 + e];
    }
#pragma unroll
    for (int off = 16; off > 0; off >>= 1)
#pragma unroll
        for (int e = 0; e < 8; e++)
            acc[e] += __shfl_xor_sync(0xffffffffu, acc[e], off);

    float alpha = alpha_p[0];
    float logits[8];
#pragma unroll
    for (int e = 0; e < 8; e++) {
        float v = (1.f - alpha) * (acc[e] + bg[e]) + alpha * tg[e];
        if (!isfinite(v)) v = 0.f;
        logits[e] = v;
    }

    float m = logits[0];
#pragma unroll
    for (int e = 1; e < 8; e++) m = fmaxf(m, logits[e]);
    float ssum = 0.f, sm[8];
#pragma unroll
    for (int e = 0; e < 8; e++) { sm[e] = expf(logits[e] - m); ssum += sm[e]; }
    float inv = 1.f / ssum;
#pragma unroll
    for (int e = 0; e < 8; e++) sm[e] *= inv;

    __shared__ float wsm[8][8];
#pragma unroll
    for (int e = 0; e < 8; e++) if (lane == e) wsm[warp][e] = sm[e];
    __syncthreads();
    if (threadIdx.x < 8) {
        float s2 = 0.f;
#pragma unroll
        for (int w = 0; w < 8; w++) s2 += wsm[w][threadIdx.x];
        g_partial[blockIdx.x * 8 + threadIdx.x] = s2;
    }

    float v0 = -1e30f; int i0 = 0;
#pragma unroll
    for (int e = 0; e < 8; e++) if (logits[e] > v0) { v0 = logits[e]; i0 = e; }
    float v1 = -1e30f; int i1 = 0;
#pragma unroll
    for (int e = 0; e < 8; e++) if (e != i0 && logits[e] > v1) { v1 = logits[e]; i1 = e; }

    float ew = expf(v1 - v0);
    float w0 = 1.f / (1.f + ew);
    float w1 = ew / (1.f + ew);

    if (lane == 0) {
        int p0 = atomicAdd(&g_cnt[i0], 1);
        int s0 = i0 * 8192 + p0;
        g_tok[s0] = t; g_w[s0] = w0;
        int p1 = atomicAdd(&g_cnt[i1], 1);
        int s1 = i1 * 8192 + p1;
        g_tok[s1] = t; g_w[s1] = w1;
    }
}

__global__ void k_laux(float* __restrict__ out, int out_size) {
    __shared__ float red[256];
    __shared__ float sw[8];
    int tid = threadIdx.x;
    int e = tid & 7, p = tid >> 3;
    float s = 0.f;
    for (int b = p; b < 1024; b += 32) s += g_partial[b * 8 + e];
    red[tid] = s;
    __syncthreads();
    if (tid < 8) {
        float t = 0.f;
        for (int q = 0; q < 32; q++) t += red[(q << 3) | tid];
        sw[tid] = t * (float)g_cnt[tid];
    }
    __syncthreads();
    if (tid == 0) {
        float l = 0.f;
        for (int i = 0; i < 8; i++) l += sw[i];
        out[out_size - 1] = l / (8192.f * 8192.f);
    }
}

// ---------------- GEMM1: 128x128xK32, 6-stage mbarrier pipeline ----------------
// Stage = A 8KB (128 rows x 64B = 4 segs, swizzle s^((r>>1)&3))
//       + B 8KB ([32 k][128 n] rows 256B = 16 segs, swizzle s^(k&7)) = 16KB; 6 stages.
// Extra blockIdx.y slice (== FDIM/128) casts W2 fp32->fp16 concurrently.
#define ST1 16384
#define B1_OFF 8192
#define MB1_OFF (6 * ST1)
#define SMEM_DYN 98432

__global__ __launch_bounds__(256, 2) void k_gemm1(const __half* __restrict__ Wh,
                                                  const float* __restrict__ bias,
                                                  const float* __restrict__ cast_src,
                                                  __half* __restrict__ cast_dst) {
    constexpr int KD = DDIM, ND = FDIM, NC = KD / 32;
    int tid = threadIdx.x;

    if (blockIdx.y == (FDIM / 128)) {
        int bid = blockIdx.x * 8 + blockIdx.z;          // 0..511
        const int chunk = CAST_N4 / 512;
        int base = bid * chunk;
#pragma unroll 4
        for (int i = base + tid; i < base + chunk; i += 256)
            cast4(cast_src, cast_dst, i);
        return;
    }

    int e = blockIdx.z;
    int cnt = g_cnt[e];
    int m0 = blockIdx.x * 128;
    if (m0 >= cnt) return;
    int n0 = blockIdx.y * 128;

    const __half* Be = Wh + (size_t)e * ((size_t)KD * ND);

    extern __shared__ char smem[];
    uint32_t sb = (smem_to_u32(smem) + 127u) & ~127u;
    uint32_t mb = sb + MB1_OFF;   // full[s]=mb+s*16, empty[s]=+8, s<6

    int lane = tid & 31, warp = tid >> 5;
    int wm = warp >> 2, wn = warp & 3;
    int gid = lane >> 2, tig = lane & 3;

    if (tid == 0) {
#pragma unroll
        for (int s = 0; s < 6; s++) {
            MBARRIER_INIT(mb + s * 16, 256);
            MBARRIER_INIT(mb + s * 16 + 8, 256);
        }
    }
    __syncthreads();

    // ---- staging (4 chunks of 16B per thread) ----
    int rA = tid >> 2, sA = tid & 3;            // A rows rA, rA+64; seg sA
    int r0 = m0 + rA, r1 = r0 + 64;
    int t0 = (r0 < cnt) ? g_tok[e * 8192 + r0] : 0;
    int t1 = (r1 < cnt) ? g_tok[e * 8192 + r1] : 0;
    const __half* srcA0 = g_xh + (size_t)t0 * KD + sA * 8;
    const __half* srcA1 = g_xh + (size_t)t1 * KD + sA * 8;
    uint32_t dA0 = (uint32_t)(rA * 64 + ((sA ^ ((rA >> 1) & 3)) << 4));
    uint32_t dA1 = dA0 + 64 * 64;
    int kB = tid >> 4, sB = tid & 15;           // B k-rows kB, kB+16; seg sB
    const __half* srcB0 = Be + (size_t)kB * ND + n0 + sB * 8;
    uint32_t dB0 = (uint32_t)(B1_OFF + kB * 256 + ((sB ^ (kB & 7)) << 4));
    uint32_t dB1 = dB0 + 16 * 256;              // (k+16)&7 == k&7

    // ---- ldmatrix addresses ----
    uint32_t addrA[4];
    {
        int grp = lane >> 3;
        int rlo = (lane & 7) + ((grp & 1) << 3);
        int segb = grp >> 1;
#pragma unroll
        for (int mi = 0; mi < 4; mi++) {
            int row = wm * 64 + mi * 16 + rlo;
            int p = (segb ^ ((row >> 1) & 3)) & 3;
            addrA[mi] = (uint32_t)(row * 64 + (p << 4));
        }
    }
    uint32_t addrB[2];
    {
        int grp = lane >> 3;
        int krow = ((grp & 1) << 3) + (lane & 7);
#pragma unroll
        for (int pr = 0; pr < 2; pr++) {
            int s = wn * 4 + pr * 2 + (grp >> 1);
            int p = s ^ (krow & 7);
            addrB[pr] = (uint32_t)(B1_OFF + krow * 256 + (p << 4));
        }
    }

    float acc[4][4][4];
#pragma unroll
    for (int mi = 0; mi < 4; mi++)
#pragma unroll
        for (int ni = 0; ni < 4; ni++)
#pragma unroll
            for (int q = 0; q < 4; q++) acc[mi][ni][q] = 0.f;

    auto issue = [&](int slot, int kt) {
        uint32_t st = sb + (uint32_t)slot * ST1;
        cp16(st + dA0, srcA0 + kt);
        cp16(st + dA1, srcA1 + kt);
        const __half* bs = srcB0 + (size_t)kt * ND;
        cp16(st + dB0, bs);
        cp16(st + dB1, bs + (size_t)16 * ND);
    };

    int pst = 0, pph = 1, cst = 0, cph = 0;

#pragma unroll
    for (int s = 0; s < 5; s++) {               // fill 5 of 6 stages
        MBARRIER_WAIT_PARITY(mb + pst * 16 + 8, pph);
        issue(pst, s * 32);
        CP_MBAR_ARRIVE(mb + pst * 16);
        if (++pst == 6) { pst = 0; pph ^= 1; }
    }

#pragma unroll 1
    for (int c = 0; c < NC; c++) {
        if (c + 5 < NC) {
            MBARRIER_WAIT_PARITY(mb + pst * 16 + 8, pph);
            issue(pst, (c + 5) * 32);
            CP_MBAR_ARRIVE(mb + pst * 16);
            if (++pst == 6) { pst = 0; pph ^= 1; }
        }
        MBARRIER_WAIT_PARITY(mb + cst * 16, cph);
        uint32_t st = sb + (uint32_t)cst * ST1;
#pragma unroll
        for (int ks = 0; ks < 2; ks++) {
            uint32_t a[4][4], b[4][2];
#pragma unroll
            for (int mi = 0; mi < 4; mi++)
                ldsm4(a[mi], st + (addrA[mi] ^ ((uint32_t)ks << 5)));
#pragma unroll
            for (int pr = 0; pr < 2; pr++) {
                uint32_t t4[4];
                ldsm4t(t4, st + addrB[pr] + (uint32_t)ks * 4096);
                b[2 * pr][0] = t4[0]; b[2 * pr][1] = t4[1];
                b[2 * pr + 1][0] = t4[2]; b[2 * pr + 1][1] = t4[3];
            }
#pragma unroll
            for (int mi = 0; mi < 4; mi++)
#pragma unroll
                for (int ni = 0; ni < 4; ni++)
                    mma16(acc[mi][ni], a[mi], b[ni]);
        }
        MBARRIER_ARRIVE(mb + cst * 16 + 8);
        if (++cst == 6) { cst = 0; cph ^= 1; }
    }

    // ---- epilogue: bias + silu -> fp16 g_h ----
    const float* bptr = bias + (size_t)e * ND;
#pragma unroll
    for (int mi = 0; mi < 4; mi++) {
        int gr0 = m0 + wm * 64 + mi * 16 + gid;
        int gr1 = gr0 + 8;
        bool v0 = gr0 < cnt, v1 = gr1 < cnt;
#pragma unroll
        for (int ni = 0; ni < 4; ni++) {
            int gc = n0 + wn * 32 + ni * 8 + tig * 2;
            float2 p0 = make_float2(acc[mi][ni][0], acc[mi][ni][1]);
            float2 p1 = make_float2(acc[mi][ni][2], acc[mi][ni][3]);
            float bb0 = bptr[gc], bb1 = bptr[gc + 1];
            p0.x += bb0; p0.y += bb1;
            p1.x += bb0; p1.y += bb1;
            p0.x = p0.x / (1.f + __expf(-p0.x));
            p0.y = p0.y / (1.f + __expf(-p0.y));
            p1.x = p1.x / (1.f + __expf(-p1.x));
            p1.y = p1.y / (1.f + __expf(-p1.y));
            __half* h0 = g_h + (size_t)(e * 8192 + gr0) * ND + gc;
            __half* h1 = g_h + (size_t)(e * 8192 + gr1) * ND + gc;
            if (v0) *(__half2*)h0 = __floats2half2_rn(p0.x, p0.y);
            if (v1) *(__half2*)h1 = __floats2half2_rn(p1.x, p1.y);
        }
    }
}

// ---------------- GEMM2: 128x128xK64, 3-stage pipeline, fused atomic combine ----
#define ST2 32768
#define B2_OFF 16384
#define MB2_OFF (3 * ST2)

__global__ __launch_bounds__(256, 2) void k_gemm2(const __half* __restrict__ Wh,
                                                  const float* __restrict__ b2,
                                                  float* __restrict__ out) {
    constexpr int KD = FDIM, ND = DDIM, NC = KD / 64;
    int tid = threadIdx.x;

    int e = blockIdx.z;
    int cnt = g_cnt[e];
    int m0 = blockIdx.x * 128;
    if (m0 >= cnt) return;
    int n0 = blockIdx.y * 128;

    const __half* Be = Wh + (size_t)e * ((size_t)KD * ND);

    extern __shared__ char smem[];
    uint32_t sb = (smem_to_u32(smem) + 127u) & ~127u;
    uint32_t mb = sb + MB2_OFF;

    int lane = tid & 31, warp = tid >> 5;
    int wm = warp >> 2, wn = warp & 3;
    int gid = lane >> 2, tig = lane & 3;

    if (tid == 0) {
#pragma unroll
        for (int s = 0; s < 3; s++) {
            MBARRIER_INIT(mb + s * 16, 256);
            MBARRIER_INIT(mb + s * 16 + 8, 256);
        }
    }
    __syncthreads();

    // ---- staging (8 chunks of 16B per thread) ----
    int rA = tid >> 2, sA = tid & 3;
    const __half* srcA0 = g_h + (size_t)(e * 8192 + m0 + rA) * KD + sA * 8;
    const __half* srcA1 = srcA0 + (size_t)64 * KD;
    uint32_t dA00 = (uint32_t)(rA * 128 + (((sA) ^ (rA & 7)) << 4));
    uint32_t dA01 = (uint32_t)(rA * 128 + (((sA + 4) ^ (rA & 7)) << 4));
    uint32_t dA10 = dA00 + 64 * 128;
    uint32_t dA11 = dA01 + 64 * 128;
    int kB = tid >> 4, sB = tid & 15;
    const __half* srcB0 = Be + (size_t)kB * ND + n0 + sB * 8;
    uint32_t dB0 = (uint32_t)(B2_OFF + kB * 256 + ((sB ^ (kB & 7)) << 4));

    // ---- ldmatrix addresses ----
    uint32_t addrA[4];
    {
        int grp = lane >> 3;
        int rlo = (lane & 7) + ((grp & 1) << 3);
        int segb = grp >> 1;
#pragma unroll
        for (int mi = 0; mi < 4; mi++) {
            int row = wm * 64 + mi * 16 + rlo;
            int p = (segb ^ (row & 7)) & 7;
            addrA[mi] = (uint32_t)(row * 128 + (p << 4));
        }
    }
    uint32_t addrB[2];
    {
        int grp = lane >> 3;
        int krow = ((grp & 1) << 3) + (lane & 7);
#pragma unroll
        for (int pr = 0; pr < 2; pr++) {
            int s = wn * 4 + pr * 2 + (grp >> 1);
            int p = s ^ (krow & 7);
            addrB[pr] = (uint32_t)(B2_OFF + krow * 256 + (p << 4));
        }
    }

    float acc[4][4][4];
#pragma unroll
    for (int mi = 0; mi < 4; mi++)
#pragma unroll
        for (int ni = 0; ni < 4; ni++)
#pragma unroll
            for (int q = 0; q < 4; q++) acc[mi][ni][q] = 0.f;

    auto issue = [&](int slot, int kt) {
        uint32_t st = sb + (uint32_t)slot * ST2;
        cp16(st + dA00, srcA0 + kt);
        cp16(st + dA01, srcA0 + kt + 32);
        cp16(st + dA10, srcA1 + kt);
        cp16(st + dA11, srcA1 + kt + 32);
        const __half* bs = srcB0 + (size_t)kt * ND;
#pragma unroll
        for (int j = 0; j < 4; j++)
            cp16(st + dB0 + (uint32_t)j * 4096, bs + (size_t)(16 * j) * ND);
    };

    int pst = 0, pph = 1, cst = 0, cph = 0;
#pragma unroll
    for (int s = 0; s < 2; s++) {
        MBARRIER_WAIT_PARITY(mb + pst * 16 + 8, pph);
        issue(pst, s * 64);
        CP_MBAR_ARRIVE(mb + pst * 16);
        if (++pst == 3) { pst = 0; pph ^= 1; }
    }

#pragma unroll 1
    for (int c = 0; c < NC; c++) {
        if (c + 2 < NC) {
            MBARRIER_WAIT_PARITY(mb + pst * 16 + 8, pph);
            issue(pst, (c + 2) * 64);
            CP_MBAR_ARRIVE(mb + pst * 16);
            if (++pst == 3) { pst = 0; pph ^= 1; }
        }
        MBARRIER_WAIT_PARITY(mb + cst * 16, cph);
        uint32_t st = sb + (uint32_t)cst * ST2;
#pragma unroll
        for (int ks = 0; ks < 4; ks++) {
            uint32_t a[4][4], b[4][2];
#pragma unroll
            for (int mi = 0; mi < 4; mi++)
                ldsm4(a[mi], st + (addrA[mi] ^ ((uint32_t)ks << 5)));
#pragma unroll
            for (int pr = 0; pr < 2; pr++) {
                uint32_t t4[4];
                ldsm4t(t4, st + addrB[pr] + (uint32_t)ks * 4096);
                b[2 * pr][0] = t4[0]; b[2 * pr][1] = t4[1];
                b[2 * pr + 1][0] = t4[2]; b[2 * pr + 1][1] = t4[3];
            }
#pragma unroll
            for (int mi = 0; mi < 4; mi++)
#pragma unroll
                for (int ni = 0; ni < 4; ni++)
                    mma16(acc[mi][ni], a[mi], b[ni]);
        }
        MBARRIER_ARRIVE(mb + cst * 16 + 8);
        if (++cst == 3) { cst = 0; cph ^= 1; }
    }

    // ---- epilogue: fused combine — out[tok] += w * (y + b2[e]) (atomic) ----
    // Each out element gets exactly 2 contributions total (top-2); fp32 add of
    // two terms is commutative, so atomic order does not change the result.
    const float* bptr = b2 + (size_t)e * ND;
#pragma unroll
    for (int mi = 0; mi < 4; mi++) {
        int gr0 = m0 + wm * 64 + mi * 16 + gid;
        int gr1 = gr0 + 8;
        bool v0 = gr0 < cnt, v1 = gr1 < cnt;
        int s0 = e * 8192 + gr0, s1 = e * 8192 + gr1;
        int tk0 = 0, tk1 = 0; float w0 = 0.f, w1 = 0.f;
        if (v0) { tk0 = g_tok[s0]; w0 = g_w[s0]; }
        if (v1) { tk1 = g_tok[s1]; w1 = g_w[s1]; }
        float* o0 = out + (size_t)tk0 * ND;
        float* o1 = out + (size_t)tk1 * ND;
#pragma unroll
        for (int ni = 0; ni < 4; ni++) {
            int gc = n0 + wn * 32 + ni * 8 + tig * 2;
            float bb0 = bptr[gc], bb1 = bptr[gc + 1];
            if (v0) {
                atomicAdd(o0 + gc,     w0 * (acc[mi][ni][0] + bb0));
                atomicAdd(o0 + gc + 1, w0 * (acc[mi][ni][1] + bb1));
            }
            if (v1) {
                atomicAdd(o1 + gc,     w1 * (acc[mi][ni][2] + bb0));
                atomicAdd(o1 + gc + 1, w1 * (acc[mi][ni][3] + bb1));
            }
        }
    }
}

// ---------------- launch ----------------
extern "C" void kernel_launch(void* const* d_in, const int* in_sizes, int n_in,
                              void* d_out, int out_size) {
    const float* inputs  = (const float*)d_in[0];
    const float* task    = (const float*)d_in[1];
    const float* Wg_in   = (const float*)d_in[2];
    const float* bg_in   = (const float*)d_in[3];
    const float* Wg_task = (const float*)d_in[4];
    const float* bg_task = (const float*)d_in[5];
    const float* alpha   = (const float*)d_in[6];
    const float* W1      = (const float*)d_in[7];
    const float* b1      = (const float*)d_in[8];
    const float* W2      = (const float*)d_in[9];
    const float* b2      = (const float*)d_in[10];
    float* out = (float*)d_out;

    cudaFuncSetAttribute(k_gemm1, cudaFuncAttributeMaxDynamicSharedMemorySize, SMEM_DYN);
    cudaFuncSetAttribute(k_gemm2, cudaFuncAttributeMaxDynamicSharedMemorySize, SMEM_DYN);

    __half* w1h_p; cudaGetSymbolAddress((void**)&w1h_p, g_w1h);
    __half* w2h_p; cudaGetSymbolAddress((void**)&w2h_p, g_w2h);

    k_init<<<1, 32>>>();
    // gate (1024) + W1 cast (32768) + out zero (8192) in one launch
    k_pregate<<<1024 + 32768 + 8192, 256>>>(inputs, Wg_in, bg_in, alpha,
                                            task, Wg_task, bg_task, W1, w1h_p, out);
    k_laux<<<1, 256>>>(out, out_size);
    // GEMM1 + W2-cast rider (blockIdx.y == 32)
    k_gemm1<<<dim3(64, FDIM / 128 + 1, NEXP), 256, SMEM_DYN>>>(w1h_p, b1, W2, w2h_p);
    // GEMM2 with fused atomic combine
    k_gemm2<<<dim3(64, DDIM / 128, NEXP), 256, SMEM_DYN>>>(w2h_p, b2, out);
}

// round 14
// speedup vs baseline: 1.0046x; 1.0046x over previous
#include <cuda_runtime.h>
#include <cuda_fp16.h>
#include <cstdint>

#define TOK   8192
#define DDIM  1024
#define FDIM  4096
#define NEXP  8
#define CAST_N4 (NEXP * DDIM * FDIM / 4)   // 8.39M float4 per weight tensor
#define OUT_N4  (TOK * DDIM / 4)           // 2.1M float4 of output to zero

// ---------------- device scratch ----------------
__device__ __half g_xh[(size_t)TOK * DDIM];             // fp16 inputs
__device__ __half g_h[(size_t)NEXP * 8192 * FDIM];      // fp16 silu(x@W1+b1)
__device__ __half g_w1h[(size_t)NEXP * DDIM * FDIM];    // W1 fp16, [K][N] layout
__device__ __half g_w2h[(size_t)NEXP * DDIM * FDIM];    // W2 fp16, [K][N] layout
__device__ int    g_tok[NEXP * 8192];
__device__ float  g_w[NEXP * 8192];
__device__ float  g_partial[1024 * NEXP];
__device__ int    g_cnt[NEXP];

// ---------------- helpers ----------------
__device__ __forceinline__ uint32_t smem_to_u32(const void* p) {
    uint32_t a;
    asm("{ .reg .u64 t; cvta.to.shared.u64 t, %1; cvt.u32.u64 %0, t; }" : "=r"(a) : "l"(p));
    return a;
}
__device__ __forceinline__ void cp16(uint32_t dst, const void* src) {
    asm volatile("cp.async.cg.shared.global [%0], [%1], 16;" :: "r"(dst), "l"(src));
}
// arrive on mbarrier when this thread's prior cp.asyncs complete (.noinc: counts
// against the init count — one tracked arrive per thread).
#define CP_MBAR_ARRIVE(mbar) \
    asm volatile("cp.async.mbarrier.arrive.noinc.shared.b64 [%0];" :: "r"((uint32_t)(mbar)) : "memory")

#define MBARRIER_INIT(mbar, count) \
    asm volatile("mbarrier.init.shared.b64 [%0], %1;" \
        :: "r"((uint32_t)(mbar)), "r"((uint32_t)(count)) : "memory")
#define MBARRIER_ARRIVE(mbar) \
    asm volatile("mbarrier.arrive.shared.b64 _, [%0];" :: "r"((uint32_t)(mbar)) : "memory")

#define MBARRIER_WAIT_PARITY(mbar_smem_addr, phase_parity) do { \
    uint32_t _mbar = (uint32_t)(mbar_smem_addr); \
    uint32_t _parity = (uint32_t)(phase_parity); \
    uint32_t _done; \
    asm volatile("{\n\t.reg .pred p;\n\t" \
        "mbarrier.try_wait.parity.acquire.cta.shared::cta.b64 p, [%1], %2;\n\t" \
        "selp.b32 %0, 1, 0, p;\n\t}" \
        : "=r"(_done) : "r"(_mbar), "r"(_parity) : "memory"); \
    if (!_done) { \
        asm volatile("{\n\t.reg .pred P1;\n\t" \
            "WAIT_LOOP_%=:\n\t" \
            "mbarrier.try_wait.parity.acquire.cta.shared::cta.b64 P1, [%0], %1, 0x989680;\n\t" \
            "@P1 bra.uni WAIT_DONE_%=;\n\t" \
            "bra.uni WAIT_LOOP_%=;\n\t" \
            "WAIT_DONE_%=:\n\t}" \
            :: "r"(_mbar), "r"(_parity) : "memory"); \
    } \
} while(0)

__device__ __forceinline__ void ldsm4(uint32_t* r, uint32_t addr) {
    asm volatile("ldmatrix.sync.aligned.m8n8.x4.shared.b16 {%0,%1,%2,%3}, [%4];"
                 : "=r"(r[0]), "=r"(r[1]), "=r"(r[2]), "=r"(r[3]) : "r"(addr));
}
__device__ __forceinline__ void ldsm4t(uint32_t* r, uint32_t addr) {
    asm volatile("ldmatrix.sync.aligned.m8n8.x4.trans.shared.b16 {%0,%1,%2,%3}, [%4];"
                 : "=r"(r[0]), "=r"(r[1]), "=r"(r[2]), "=r"(r[3]) : "r"(addr));
}
// fp16 MMA, fp32 accumulate: D(16x8) += A(16x16) * B(16x8)
__device__ __forceinline__ void mma16(float* d, const uint32_t* a, const uint32_t* b) {
    asm("mma.sync.aligned.m16n8k16.row.col.f32.f16.f16.f32 "
        "{%0,%1,%2,%3}, {%4,%5,%6,%7}, {%8,%9}, {%0,%1,%2,%3};"
        : "+f"(d[0]), "+f"(d[1]), "+f"(d[2]), "+f"(d[3])
        : "r"(a[0]), "r"(a[1]), "r"(a[2]), "r"(a[3]), "r"(b[0]), "r"(b[1]));
}

__device__ __forceinline__ void cast4(const float* __restrict__ src,
                                      __half* __restrict__ dst, int i) {
    float4 v = ((const float4*)src)[i];
    __half2 h0 = __floats2half2_rn(v.x, v.y);
    __half2 h1 = __floats2half2_rn(v.z, v.w);
    uint2 u;
    u.x = *(uint32_t*)&h0;
    u.y = *(uint32_t*)&h1;
    ((uint2*)dst)[i] = u;
}

// ---------------- small kernels ----------------
__global__ void k_init() {
    if (threadIdx.x < NEXP) g_cnt[threadIdx.x] = 0;
}

// mega pre-kernel: blocks [0,1024) = gating (task-gate inline);
// blocks [1024, 1024+32768) = W1 cast; blocks [33792, 33792+8192) = zero out.
__global__ void k_pregate(const float* __restrict__ x,
                          const float* __restrict__ Wg,
                          const float* __restrict__ bg,
                          const float* __restrict__ alpha_p,
                          const float* __restrict__ task,
                          const float* __restrict__ Wgt,
                          const float* __restrict__ bgt,
                          const float* __restrict__ W1,
                          __half* __restrict__ w1h,
                          float* __restrict__ out) {
    if (blockIdx.x >= 1024 + 32768) {
        int i = (blockIdx.x - 1024 - 32768) * 256 + threadIdx.x;
        if (i < OUT_N4) ((float4*)out)[i] = make_float4(0.f, 0.f, 0.f, 0.f);
        return;
    }
    if (blockIdx.x >= 1024) {
        int i = (blockIdx.x - 1024) * 256 + threadIdx.x;
        if (i < CAST_N4) cast4(W1, w1h, i);
        return;
    }

    // ---- inline task gate ----
    __shared__ float red[256][8];
    __shared__ float tg[8];
    {
        float p[8];
#pragma unroll
        for (int e = 0; e < 8; e++) p[e] = 0.f;
        for (int d = threadIdx.x; d < DDIM; d += 256) {
            float tv = task[d];
#pragma unroll
            for (int e = 0; e < 8; e++) p[e] += tv * Wgt[d * 8 + e];
        }
#pragma unroll
        for (int e = 0; e < 8; e++) red[threadIdx.x][e] = p[e];
        __syncthreads();
        if (threadIdx.x < 8) {
            float s = bgt[threadIdx.x];
            for (int w = 0; w < 256; w++) s += red[w][threadIdx.x];
            tg[threadIdx.x] = s;
        }
        __syncthreads();
    }

    // ---- per-token gating: one warp per token ----
    int warp = threadIdx.x >> 5, lane = threadIdx.x & 31;
    int t = blockIdx.x * 8 + warp;
    const float* xr = x + (size_t)t * DDIM;
    __half* xw = g_xh + (size_t)t * DDIM;

    float acc[8];
#pragma unroll
    for (int e = 0; e < 8; e++) acc[e] = 0.f;
#pragma unroll 4
    for (int i = 0; i < 32; i++) {
        int d = i * 32 + lane;
        float xv = xr[d];
        xw[d] = __float2half_rn(xv);
#pragma unroll
        for (int e = 0; e < 8; e++) acc[e] += xv * Wg[d * 8 + e];
    }
#pragma unroll
    for (int off = 16; off > 0; off >>= 1)
#pragma unroll
        for (int e = 0; e < 8; e++)
            acc[e] += __shfl_xor_sync(0xffffffffu, acc[e], off);

    float alpha = alpha_p[0];
    float logits[8];
#pragma unroll
    for (int e = 0; e < 8; e++) {
        float v = (1.f - alpha) * (acc[e] + bg[e]) + alpha * tg[e];
        if (!isfinite(v)) v = 0.f;
        logits[e] = v;
    }

    float m = logits[0];
#pragma unroll
    for (int e = 1; e < 8; e++) m = fmaxf(m, logits[e]);
    float ssum = 0.f, sm[8];
#pragma unroll
    for (int e = 0; e < 8; e++) { sm[e] = expf(logits[e] - m); ssum += sm[e]; }
    float inv = 1.f / ssum;
#pragma unroll
    for (int e = 0; e < 8; e++) sm[e] *= inv;

    __shared__ float wsm[8][8];
#pragma unroll
    for (int e = 0; e < 8; e++) if (lane == e) wsm[warp][e] = sm[e];
    __syncthreads();
    if (threadIdx.x < 8) {
        float s2 = 0.f;
#pragma unroll
        for (int w = 0; w < 8; w++) s2 += wsm[w][threadIdx.x];
        g_partial[blockIdx.x * 8 + threadIdx.x] = s2;
    }

    float v0 = -1e30f; int i0 = 0;
#pragma unroll
    for (int e = 0; e < 8; e++) if (logits[e] > v0) { v0 = logits[e]; i0 = e; }
    float v1 = -1e30f; int i1 = 0;
#pragma unroll
    for (int e = 0; e < 8; e++) if (e != i0 && logits[e] > v1) { v1 = logits[e]; i1 = e; }

    float ew = expf(v1 - v0);
    float w0 = 1.f / (1.f + ew);
    float w1 = ew / (1.f + ew);

    if (lane == 0) {
        int p0 = atomicAdd(&g_cnt[i0], 1);
        int s0 = i0 * 8192 + p0;
        g_tok[s0] = t; g_w[s0] = w0;
        int p1 = atomicAdd(&g_cnt[i1], 1);
        int s1 = i1 * 8192 + p1;
        g_tok[s1] = t; g_w[s1] = w1;
    }
}

__global__ void k_laux(float* __restrict__ out, int out_size) {
    __shared__ float red[256];
    __shared__ float sw[8];
    int tid = threadIdx.x;
    int e = tid & 7, p = tid >> 3;
    float s = 0.f;
    for (int b = p; b < 1024; b += 32) s += g_partial[b * 8 + e];
    red[tid] = s;
    __syncthreads();
    if (tid < 8) {
        float t = 0.f;
        for (int q = 0; q < 32; q++) t += red[(q << 3) | tid];
        sw[tid] = t * (float)g_cnt[tid];
    }
    __syncthreads();
    if (tid == 0) {
        float l = 0.f;
        for (int i = 0; i < 8; i++) l += sw[i];
        out[out_size - 1] = l / (8192.f * 8192.f);
    }
}

// ---------------- GEMM common shape: 128x128xK64, 3-stage mbarrier pipeline ----
// Stage = A 16KB (rows 128B = 8 segs, swizzle s^(r&7))
//       + B 16KB ([64 k][128 n] rows 256B = 16 segs, swizzle s^(k&7)) = 32KB.
#define STAGE_BYTES 32768
#define B_OFF 16384
#define MB_OFF (3 * STAGE_BYTES)
#define SMEM_DYN (3 * STAGE_BYTES + 128)

// ---------------- GEMM1 (+ W2-cast rider on blockIdx.y == FDIM/128) ----------
__global__ __launch_bounds__(256, 2) void k_gemm1(const __half* __restrict__ Wh,
                                                  const float* __restrict__ bias,
                                                  const float* __restrict__ cast_src,
                                                  __half* __restrict__ cast_dst) {
    constexpr int KD = DDIM, ND = FDIM, NC = KD / 64;
    int tid = threadIdx.x;

    if (blockIdx.y == (FDIM / 128)) {
        int bid = blockIdx.x * 8 + blockIdx.z;          // 0..511
        const int chunk = CAST_N4 / 512;
        int base = bid * chunk;
#pragma unroll 4
        for (int i = base + tid; i < base + chunk; i += 256)
            cast4(cast_src, cast_dst, i);
        return;
    }

    int e = blockIdx.z;
    int cnt = g_cnt[e];
    int m0 = blockIdx.x * 128;
    if (m0 >= cnt) return;
    int n0 = blockIdx.y * 128;

    const __half* Be = Wh + (size_t)e * ((size_t)KD * ND);

    extern __shared__ char smem[];
    uint32_t sb = (smem_to_u32(smem) + 127u) & ~127u;
    uint32_t mb = sb + MB_OFF;

    int lane = tid & 31, warp = tid >> 5;
    int wm = warp >> 2, wn = warp & 3;
    int gid = lane >> 2, tig = lane & 3;

    if (tid == 0) {
#pragma unroll
        for (int s = 0; s < 3; s++) {
            MBARRIER_INIT(mb + s * 16, 256);
            MBARRIER_INIT(mb + s * 16 + 8, 256);
        }
    }
    __syncthreads();

    // ---- staging (8 chunks of 16B per thread) ----
    int rA = tid >> 2, sA = tid & 3;
    int r0 = m0 + rA, r1 = r0 + 64;
    int t0 = (r0 < cnt) ? g_tok[e * 8192 + r0] : 0;
    int t1 = (r1 < cnt) ? g_tok[e * 8192 + r1] : 0;
    const __half* srcA0 = g_xh + (size_t)t0 * KD + sA * 8;
    const __half* srcA1 = g_xh + (size_t)t1 * KD + sA * 8;
    uint32_t dA00 = (uint32_t)(rA * 128 + (((sA) ^ (rA & 7)) << 4));
    uint32_t dA01 = (uint32_t)(rA * 128 + (((sA + 4) ^ (rA & 7)) << 4));
    uint32_t dA10 = dA00 + 64 * 128;
    uint32_t dA11 = dA01 + 64 * 128;
    int kB = tid >> 4, sB = tid & 15;
    const __half* srcB0 = Be + (size_t)kB * ND + n0 + sB * 8;
    uint32_t dB0 = (uint32_t)(B_OFF + kB * 256 + ((sB ^ (kB & 7)) << 4));

    // ---- ldmatrix addresses ----
    uint32_t addrA[4];
    {
        int grp = lane >> 3;
        int rlo = (lane & 7) + ((grp & 1) << 3);
        int segb = grp >> 1;
#pragma unroll
        for (int mi = 0; mi < 4; mi++) {
            int row = wm * 64 + mi * 16 + rlo;
            int p = (segb ^ (row & 7)) & 7;
            addrA[mi] = (uint32_t)(row * 128 + (p << 4));
        }
    }
    uint32_t addrB[2];
    {
        int grp = lane >> 3;
        int krow = ((grp & 1) << 3) + (lane & 7);
#pragma unroll
        for (int pr = 0; pr < 2; pr++) {
            int s = wn * 4 + pr * 2 + (grp >> 1);
            int p = s ^ (krow & 7);
            addrB[pr] = (uint32_t)(B_OFF + krow * 256 + (p << 4));
        }
    }

    float acc[4][4][4];
#pragma unroll
    for (int mi = 0; mi < 4; mi++)
#pragma unroll
        for (int ni = 0; ni < 4; ni++)
#pragma unroll
            for (int q = 0; q < 4; q++) acc[mi][ni][q] = 0.f;

    auto issue = [&](int slot, int kt) {
        uint32_t st = sb + (uint32_t)slot * STAGE_BYTES;
        cp16(st + dA00, srcA0 + kt);
        cp16(st + dA01, srcA0 + kt + 32);
        cp16(st + dA10, srcA1 + kt);
        cp16(st + dA11, srcA1 + kt + 32);
        const __half* bs = srcB0 + (size_t)kt * ND;
#pragma unroll
        for (int j = 0; j < 4; j++)
            cp16(st + dB0 + (uint32_t)j * 4096, bs + (size_t)(16 * j) * ND);
    };

    int pst = 0, pph = 1, cst = 0, cph = 0;
#pragma unroll
    for (int s = 0; s < 2; s++) {
        MBARRIER_WAIT_PARITY(mb + pst * 16 + 8, pph);
        issue(pst, s * 64);
        CP_MBAR_ARRIVE(mb + pst * 16);
        if (++pst == 3) { pst = 0; pph ^= 1; }
    }

#pragma unroll 1
    for (int c = 0; c < NC; c++) {
        if (c + 2 < NC) {
            MBARRIER_WAIT_PARITY(mb + pst * 16 + 8, pph);
            issue(pst, (c + 2) * 64);
            CP_MBAR_ARRIVE(mb + pst * 16);
            if (++pst == 3) { pst = 0; pph ^= 1; }
        }
        MBARRIER_WAIT_PARITY(mb + cst * 16, cph);
        uint32_t st = sb + (uint32_t)cst * STAGE_BYTES;
#pragma unroll
        for (int ks = 0; ks < 4; ks++) {
            uint32_t a[4][4], b[4][2];
#pragma unroll
            for (int mi = 0; mi < 4; mi++)
                ldsm4(a[mi], st + (addrA[mi] ^ ((uint32_t)ks << 5)));
#pragma unroll
            for (int pr = 0; pr < 2; pr++) {
                uint32_t t4[4];
                ldsm4t(t4, st + addrB[pr] + (uint32_t)ks * 4096);
                b[2 * pr][0] = t4[0]; b[2 * pr][1] = t4[1];
                b[2 * pr + 1][0] = t4[2]; b[2 * pr + 1][1] = t4[3];
            }
#pragma unroll
            for (int mi = 0; mi < 4; mi++)
#pragma unroll
                for (int ni = 0; ni < 4; ni++)
                    mma16(acc[mi][ni], a[mi], b[ni]);
        }
        MBARRIER_ARRIVE(mb + cst * 16 + 8);
        if (++cst == 3) { cst = 0; cph ^= 1; }
    }

    // ---- epilogue: bias + silu -> fp16 g_h ----
    const float* bptr = bias + (size_t)e * ND;
#pragma unroll
    for (int mi = 0; mi < 4; mi++) {
        int gr0 = m0 + wm * 64 + mi * 16 + gid;
        int gr1 = gr0 + 8;
        bool v0 = gr0 < cnt, v1 = gr1 < cnt;
#pragma unroll
        for (int ni = 0; ni < 4; ni++) {
            int gc = n0 + wn * 32 + ni * 8 + tig * 2;
            float2 p0 = make_float2(acc[mi][ni][0], acc[mi][ni][1]);
            float2 p1 = make_float2(acc[mi][ni][2], acc[mi][ni][3]);
            float bb0 = bptr[gc], bb1 = bptr[gc + 1];
            p0.x += bb0; p0.y += bb1;
            p1.x += bb0; p1.y += bb1;
            p0.x = p0.x / (1.f + __expf(-p0.x));
            p0.y = p0.y / (1.f + __expf(-p0.y));
            p1.x = p1.x / (1.f + __expf(-p1.x));
            p1.y = p1.y / (1.f + __expf(-p1.y));
            __half* h0 = g_h + (size_t)(e * 8192 + gr0) * ND + gc;
            __half* h1 = g_h + (size_t)(e * 8192 + gr1) * ND + gc;
            if (v0) *(__half2*)h0 = __floats2half2_rn(p0.x, p0.y);
            if (v1) *(__half2*)h1 = __floats2half2_rn(p1.x, p1.y);
        }
    }
}

// ---------------- GEMM2: fused atomic combine epilogue -----------------------
__global__ __launch_bounds__(256, 2) void k_gemm2(const __half* __restrict__ Wh,
                                                  const float* __restrict__ b2,
                                                  float* __restrict__ out) {
    constexpr int KD = FDIM, ND = DDIM, NC = KD / 64;
    int tid = threadIdx.x;

    int e = blockIdx.z;
    int cnt = g_cnt[e];
    int m0 = blockIdx.x * 128;
    if (m0 >= cnt) return;
    int n0 = blockIdx.y * 128;

    const __half* Be = Wh + (size_t)e * ((size_t)KD * ND);

    extern __shared__ char smem[];
    uint32_t sb = (smem_to_u32(smem) + 127u) & ~127u;
    uint32_t mb = sb + MB_OFF;

    int lane = tid & 31, warp = tid >> 5;
    int wm = warp >> 2, wn = warp & 3;
    int gid = lane >> 2, tig = lane & 3;

    if (tid == 0) {
#pragma unroll
        for (int s = 0; s < 3; s++) {
            MBARRIER_INIT(mb + s * 16, 256);
            MBARRIER_INIT(mb + s * 16 + 8, 256);
        }
    }
    __syncthreads();

    // ---- staging (8 chunks of 16B per thread) ----
    int rA = tid >> 2, sA = tid & 3;
    const __half* srcA0 = g_h + (size_t)(e * 8192 + m0 + rA) * KD + sA * 8;
    const __half* srcA1 = srcA0 + (size_t)64 * KD;
    uint32_t dA00 = (uint32_t)(rA * 128 + (((sA) ^ (rA & 7)) << 4));
    uint32_t dA01 = (uint32_t)(rA * 128 + (((sA + 4) ^ (rA & 7)) << 4));
    uint32_t dA10 = dA00 + 64 * 128;
    uint32_t dA11 = dA01 + 64 * 128;
    int kB = tid >> 4, sB = tid & 15;
    const __half* srcB0 = Be + (size_t)kB * ND + n0 + sB * 8;
    uint32_t dB0 = (uint32_t)(B_OFF + kB * 256 + ((sB ^ (kB & 7)) << 4));

    // ---- ldmatrix addresses ----
    uint32_t addrA[4];
    {
        int grp = lane >> 3;
        int rlo = (lane & 7) + ((grp & 1) << 3);
        int segb = grp >> 1;
#pragma unroll
        for (int mi = 0; mi < 4; mi++) {
            int row = wm * 64 + mi * 16 + rlo;
            int p = (segb ^ (row & 7)) & 7;
            addrA[mi] = (uint32_t)(row * 128 + (p << 4));
        }
    }
    uint32_t addrB[2];
    {
        int grp = lane >> 3;
        int krow = ((grp & 1) << 3) + (lane & 7);
#pragma unroll
        for (int pr = 0; pr < 2; pr++) {
            int s = wn * 4 + pr * 2 + (grp >> 1);
            int p = s ^ (krow & 7);
            addrB[pr] = (uint32_t)(B_OFF + krow * 256 + (p << 4));
        }
    }

    float acc[4][4][4];
#pragma unroll
    for (int mi = 0; mi < 4; mi++)
#pragma unroll
        for (int ni = 0; ni < 4; ni++)
#pragma unroll
            for (int q = 0; q < 4; q++) acc[mi][ni][q] = 0.f;

    auto issue = [&](int slot, int kt) {
        uint32_t st = sb + (uint32_t)slot * STAGE_BYTES;
        cp16(st + dA00, srcA0 + kt);
        cp16(st + dA01, srcA0 + kt + 32);
        cp16(st + dA10, srcA1 + kt);
        cp16(st + dA11, srcA1 + kt + 32);
        const __half* bs = srcB0 + (size_t)kt * ND;
#pragma unroll
        for (int j = 0; j < 4; j++)
            cp16(st + dB0 + (uint32_t)j * 4096, bs + (size_t)(16 * j) * ND);
    };

    int pst = 0, pph = 1, cst = 0, cph = 0;
#pragma unroll
    for (int s = 0; s < 2; s++) {
        MBARRIER_WAIT_PARITY(mb + pst * 16 + 8, pph);
        issue(pst, s * 64);
        CP_MBAR_ARRIVE(mb + pst * 16);
        if (++pst == 3) { pst = 0; pph ^= 1; }
    }

#pragma unroll 1
    for (int c = 0; c < NC; c++) {
        if (c + 2 < NC) {
            MBARRIER_WAIT_PARITY(mb + pst * 16 + 8, pph);
            issue(pst, (c + 2) * 64);
            CP_MBAR_ARRIVE(mb + pst * 16);
            if (++pst == 3) { pst = 0; pph ^= 1; }
        }
        MBARRIER_WAIT_PARITY(mb + cst * 16, cph);
        uint32_t st = sb + (uint32_t)cst * STAGE_BYTES;
#pragma unroll
        for (int ks = 0; ks < 4; ks++) {
            uint32_t a[4][4], b[4][2];
#pragma unroll
            for (int mi = 0; mi < 4; mi++)
                ldsm4(a[mi], st + (addrA[mi] ^ ((uint32_t)ks << 5)));
#pragma unroll
            for (int pr = 0; pr < 2; pr++) {
                uint32_t t4[4];
                ldsm4t(t4, st + addrB[pr] + (uint32_t)ks * 4096);
                b[2 * pr][0] = t4[0]; b[2 * pr][1] = t4[1];
                b[2 * pr + 1][0] = t4[2]; b[2 * pr + 1][1] = t4[3];
            }
#pragma unroll
            for (int mi = 0; mi < 4; mi++)
#pragma unroll
                for (int ni = 0; ni < 4; ni++)
                    mma16(acc[mi][ni], a[mi], b[ni]);
        }
        MBARRIER_ARRIVE(mb + cst * 16 + 8);
        if (++cst == 3) { cst = 0; cph ^= 1; }
    }

    // ---- epilogue: fused combine — out[tok] += w * (y + b2[e]) (atomic) ----
    // Each out element gets exactly 2 contributions total (top-2); fp32 add of
    // two terms is commutative, so atomic order does not change the result.
    const float* bptr = b2 + (size_t)e * ND;
#pragma unroll
    for (int mi = 0; mi < 4; mi++) {
        int gr0 = m0 + wm * 64 + mi * 16 + gid;
        int gr1 = gr0 + 8;
        bool v0 = gr0 < cnt, v1 = gr1 < cnt;
        int s0 = e * 8192 + gr0, s1 = e * 8192 + gr1;
        int tk0 = 0, tk1 = 0; float w0 = 0.f, w1 = 0.f;
        if (v0) { tk0 = g_tok[s0]; w0 = g_w[s0]; }
        if (v1) { tk1 = g_tok[s1]; w1 = g_w[s1]; }
        float* o0 = out + (size_t)tk0 * ND;
        float* o1 = out + (size_t)tk1 * ND;
#pragma unroll
        for (int ni = 0; ni < 4; ni++) {
            int gc = n0 + wn * 32 + ni * 8 + tig * 2;
            float bb0 = bptr[gc], bb1 = bptr[gc + 1];
            if (v0) {
                atomicAdd(o0 + gc,     w0 * (acc[mi][ni][0] + bb0));
                atomicAdd(o0 + gc + 1, w0 * (acc[mi][ni][1] + bb1));
            }
            if (v1) {
                atomicAdd(o1 + gc,     w1 * (acc[mi][ni][2] + bb0));
                atomicAdd(o1 + gc + 1, w1 * (acc[mi][ni][3] + bb1));
            }
        }
    }
}

// ---------------- launch ----------------
extern "C" void kernel_launch(void* const* d_in, const int* in_sizes, int n_in,
                              void* d_out, int out_size) {
    const float* inputs  = (const float*)d_in[0];
    const float* task    = (const float*)d_in[1];
    const float* Wg_in   = (const float*)d_in[2];
    const float* bg_in   = (const float*)d_in[3];
    const float* Wg_task = (const float*)d_in[4];
    const float* bg_task = (const float*)d_in[5];
    const float* alpha   = (const float*)d_in[6];
    const float* W1      = (const float*)d_in[7];
    const float* b1      = (const float*)d_in[8];
    const float* W2      = (const float*)d_in[9];
    const float* b2      = (const float*)d_in[10];
    float* out = (float*)d_out;

    cudaFuncSetAttribute(k_gemm1, cudaFuncAttributeMaxDynamicSharedMemorySize, SMEM_DYN);
    cudaFuncSetAttribute(k_gemm2, cudaFuncAttributeMaxDynamicSharedMemorySize, SMEM_DYN);

    __half* w1h_p; cudaGetSymbolAddress((void**)&w1h_p, g_w1h);
    __half* w2h_p; cudaGetSymbolAddress((void**)&w2h_p, g_w2h);

    k_init<<<1, 32>>>();
    // gate (1024) + W1 cast (32768) + out zero (8192) in one launch
    k_pregate<<<1024 + 32768 + 8192, 256>>>(inputs, Wg_in, bg_in, alpha,
                                            task, Wg_task, bg_task, W1, w1h_p, out);
    k_laux<<<1, 256>>>(out, out_size);
    // GEMM1 (chunk-64, 3-stage) + W2-cast rider (blockIdx.y == 32)
    k_gemm1<<<dim3(64, FDIM / 128 + 1, NEXP), 256, SMEM_DYN>>>(w1h_p, b1, W2, w2h_p);
    // GEMM2 (chunk-64, 3-stage) with fused atomic combine
    k_gemm2<<<dim3(64, DDIM / 128, NEXP), 256, SMEM_DYN>>>(w2h_p, b2, out);
}

// round 15
// speedup vs baseline: 1.0335x; 1.0288x over previous
#include <cuda_runtime.h>
#include <cuda_fp16.h>
#include <cstdint>

#define TOK   8192
#define DDIM  1024
#define FDIM  4096
#define NEXP  8
#define CAST_N4 (NEXP * DDIM * FDIM / 4)   // 8.39M float4 per weight tensor

// ---------------- device scratch ----------------
__device__ __half g_xh[(size_t)TOK * DDIM];             // fp16 inputs
__device__ __half g_h[(size_t)NEXP * 8192 * FDIM];      // fp16 silu(x@W1+b1)
__device__ float  g_y[(size_t)NEXP * 8192 * DDIM];      // raw expert output (fp32)
__device__ __half g_w1h[(size_t)NEXP * DDIM * FDIM];    // W1 fp16, [K][N] layout
__device__ __half g_w2h[(size_t)NEXP * DDIM * FDIM];    // W2 fp16, [K][N] layout
__device__ int    g_tok[NEXP * 8192];
__device__ float  g_w[NEXP * 8192];
__device__ int    g_slot[TOK * 2];
__device__ float  g_partial[1024 * NEXP];
__device__ int    g_cnt[NEXP];

// ---------------- helpers ----------------
__device__ __forceinline__ uint32_t smem_to_u32(const void* p) {
    uint32_t a;
    asm("{ .reg .u64 t; cvta.to.shared.u64 t, %1; cvt.u32.u64 %0, t; }" : "=r"(a) : "l"(p));
    return a;
}
__device__ __forceinline__ void cp16(uint32_t dst, const void* src) {
    asm volatile("cp.async.cg.shared.global [%0], [%1], 16;" :: "r"(dst), "l"(src));
}
// arrive on mbarrier when this thread's prior cp.asyncs complete (.noinc: counts
// against the init count — one tracked arrive per thread).
#define CP_MBAR_ARRIVE(mbar) \
    asm volatile("cp.async.mbarrier.arrive.noinc.shared.b64 [%0];" :: "r"((uint32_t)(mbar)) : "memory")

#define MBARRIER_INIT(mbar, count) \
    asm volatile("mbarrier.init.shared.b64 [%0], %1;" \
        :: "r"((uint32_t)(mbar)), "r"((uint32_t)(count)) : "memory")
#define MBARRIER_ARRIVE(mbar) \
    asm volatile("mbarrier.arrive.shared.b64 _, [%0];" :: "r"((uint32_t)(mbar)) : "memory")

#define MBARRIER_WAIT_PARITY(mbar_smem_addr, phase_parity) do { \
    uint32_t _mbar = (uint32_t)(mbar_smem_addr); \
    uint32_t _parity = (uint32_t)(phase_parity); \
    uint32_t _done; \
    asm volatile("{\n\t.reg .pred p;\n\t" \
        "mbarrier.try_wait.parity.acquire.cta.shared::cta.b64 p, [%1], %2;\n\t" \
        "selp.b32 %0, 1, 0, p;\n\t}" \
        : "=r"(_done) : "r"(_mbar), "r"(_parity) : "memory"); \
    if (!_done) { \
        asm volatile("{\n\t.reg .pred P1;\n\t" \
            "WAIT_LOOP_%=:\n\t" \
            "mbarrier.try_wait.parity.acquire.cta.shared::cta.b64 P1, [%0], %1, 0x989680;\n\t" \
            "@P1 bra.uni WAIT_DONE_%=;\n\t" \
            "bra.uni WAIT_LOOP_%=;\n\t" \
            "WAIT_DONE_%=:\n\t}" \
            :: "r"(_mbar), "r"(_parity) : "memory"); \
    } \
} while(0)

__device__ __forceinline__ void ldsm4(uint32_t* r, uint32_t addr) {
    asm volatile("ldmatrix.sync.aligned.m8n8.x4.shared.b16 {%0,%1,%2,%3}, [%4];"
                 : "=r"(r[0]), "=r"(r[1]), "=r"(r[2]), "=r"(r[3]) : "r"(addr));
}
__device__ __forceinline__ void ldsm4t(uint32_t* r, uint32_t addr) {
    asm volatile("ldmatrix.sync.aligned.m8n8.x4.trans.shared.b16 {%0,%1,%2,%3}, [%4];"
                 : "=r"(r[0]), "=r"(r[1]), "=r"(r[2]), "=r"(r[3]) : "r"(addr));
}
// fp16 MMA, fp32 accumulate: D(16x8) += A(16x16) * B(16x8)
__device__ __forceinline__ void mma16(float* d, const uint32_t* a, const uint32_t* b) {
    asm("mma.sync.aligned.m16n8k16.row.col.f32.f16.f16.f32 "
        "{%0,%1,%2,%3}, {%4,%5,%6,%7}, {%8,%9}, {%0,%1,%2,%3};"
        : "+f"(d[0]), "+f"(d[1]), "+f"(d[2]), "+f"(d[3])
        : "r"(a[0]), "r"(a[1]), "r"(a[2]), "r"(a[3]), "r"(b[0]), "r"(b[1]));
}

__device__ __forceinline__ void cast4(const float* __restrict__ src,
                                      __half* __restrict__ dst, int i) {
    float4 v = ((const float4*)src)[i];
    __half2 h0 = __floats2half2_rn(v.x, v.y);
    __half2 h1 = __floats2half2_rn(v.z, v.w);
    uint2 u;
    u.x = *(uint32_t*)&h0;
    u.y = *(uint32_t*)&h1;
    ((uint2*)dst)[i] = u;
}

// silu via single-instruction HW tanh: x * 0.5 * (1 + tanh(x/2))
__device__ __forceinline__ float silu_f(float x) {
    float t;
    asm("tanh.approx.f32 %0, %1;" : "=f"(t) : "f"(x * 0.5f));
    return x * 0.5f * (1.f + t);
}

// ---------------- small kernels ----------------
__global__ void k_init() {
    if (threadIdx.x < NEXP) g_cnt[threadIdx.x] = 0;
}

// mega pre-kernel: blocks [0,1024) = gating (task-gate inline);
// blocks [1024, 1024+32768) = W1 fp32->fp16 cast.
__global__ void k_pregate(const float* __restrict__ x,
                          const float* __restrict__ Wg,
                          const float* __restrict__ bg,
                          const float* __restrict__ alpha_p,
                          const float* __restrict__ task,
                          const float* __restrict__ Wgt,
                          const float* __restrict__ bgt,
                          const float* __restrict__ W1,
                          __half* __restrict__ w1h) {
    if (blockIdx.x >= 1024) {
        int i = (blockIdx.x - 1024) * 256 + threadIdx.x;
        if (i < CAST_N4) cast4(W1, w1h, i);
        return;
    }

    // ---- inline task gate ----
    __shared__ float red[256][8];
    __shared__ float tg[8];
    {
        float p[8];
#pragma unroll
        for (int e = 0; e < 8; e++) p[e] = 0.f;
        for (int d = threadIdx.x; d < DDIM; d += 256) {
            float tv = task[d];
#pragma unroll
            for (int e = 0; e < 8; e++) p[e] += tv * Wgt[d * 8 + e];
        }
#pragma unroll
        for (int e = 0; e < 8; e++) red[threadIdx.x][e] = p[e];
        __syncthreads();
        if (threadIdx.x < 8) {
            float s = bgt[threadIdx.x];
            for (int w = 0; w < 256; w++) s += red[w][threadIdx.x];
            tg[threadIdx.x] = s;
        }
        __syncthreads();
    }

    // ---- per-token gating: one warp per token ----
    int warp = threadIdx.x >> 5, lane = threadIdx.x & 31;
    int t = blockIdx.x * 8 + warp;
    const float* xr = x + (size_t)t * DDIM;
    __half* xw = g_xh + (size_t)t * DDIM;

    float acc[8];
#pragma unroll
    for (int e = 0; e < 8; e++) acc[e] = 0.f;
#pragma unroll 4
    for (int i = 0; i < 32; i++) {
        int d = i * 32 + lane;
        float xv = xr[d];
        xw[d] = __float2half_rn(xv);
#pragma unroll
        for (int e = 0; e < 8; e++) acc[e] += xv * Wg[d * 8 + e];
    }
#pragma unroll
    for (int off = 16; off > 0; off >>= 1)
#pragma unroll
        for (int e = 0; e < 8; e++)
            acc[e] += __shfl_xor_sync(0xffffffffu, acc[e], off);

    float alpha = alpha_p[0];
    float logits[8];
#pragma unroll
    for (int e = 0; e < 8; e++) {
        float v = (1.f - alpha) * (acc[e] + bg[e]) + alpha * tg[e];
        if (!isfinite(v)) v = 0.f;
        logits[e] = v;
    }

    float m = logits[0];
#pragma unroll
    for (int e = 1; e < 8; e++) m = fmaxf(m, logits[e]);
    float ssum = 0.f, sm[8];
#pragma unroll
    for (int e = 0; e < 8; e++) { sm[e] = expf(logits[e] - m); ssum += sm[e]; }
    float inv = 1.f / ssum;
#pragma unroll
    for (int e = 0; e < 8; e++) sm[e] *= inv;

    __shared__ float wsm[8][8];
#pragma unroll
    for (int e = 0; e < 8; e++) if (lane == e) wsm[warp][e] = sm[e];
    __syncthreads();
    if (threadIdx.x < 8) {
        float s2 = 0.f;
#pragma unroll
        for (int w = 0; w < 8; w++) s2 += wsm[w][threadIdx.x];
        g_partial[blockIdx.x * 8 + threadIdx.x] = s2;
    }

    float v0 = -1e30f; int i0 = 0;
#pragma unroll
    for (int e = 0; e < 8; e++) if (logits[e] > v0) { v0 = logits[e]; i0 = e; }
    float v1 = -1e30f; int i1 = 0;
#pragma unroll
    for (int e = 0; e < 8; e++) if (e != i0 && logits[e] > v1) { v1 = logits[e]; i1 = e; }

    float ew = expf(v1 - v0);
    float w0 = 1.f / (1.f + ew);
    float w1 = ew / (1.f + ew);

    if (lane == 0) {
        int p0 = atomicAdd(&g_cnt[i0], 1);
        int s0 = i0 * 8192 + p0;
        g_tok[s0] = t; g_w[s0] = w0; g_slot[t * 2 + 0] = s0;
        int p1 = atomicAdd(&g_cnt[i1], 1);
        int s1 = i1 * 8192 + p1;
        g_tok[s1] = t; g_w[s1] = w1; g_slot[t * 2 + 1] = s1;
    }
}

__global__ void k_laux(float* __restrict__ out, int out_size) {
    __shared__ float red[256];
    __shared__ float sw[8];
    int tid = threadIdx.x;
    int e = tid & 7, p = tid >> 3;
    float s = 0.f;
    for (int b = p; b < 1024; b += 32) s += g_partial[b * 8 + e];
    red[tid] = s;
    __syncthreads();
    if (tid < 8) {
        float t = 0.f;
        for (int q = 0; q < 32; q++) t += red[(q << 3) | tid];
        sw[tid] = t * (float)g_cnt[tid];
    }
    __syncthreads();
    if (tid == 0) {
        float l = 0.f;
        for (int i = 0; i < 8; i++) l += sw[i];
        out[out_size - 1] = l / (8192.f * 8192.f);
    }
}

// ---------------- GEMM common shape: 128x128xK64, 3-stage mbarrier pipeline ----
#define STAGE_BYTES 32768
#define B_OFF 16384
#define MB_OFF (3 * STAGE_BYTES)
#define SMEM_DYN (3 * STAGE_BYTES + 128)

// ---------------- GEMM1 (+ W2-cast rider on blockIdx.y == FDIM/128) ----------
__global__ __launch_bounds__(256, 2) void k_gemm1(const __half* __restrict__ Wh,
                                                  const float* __restrict__ bias,
                                                  const float* __restrict__ cast_src,
                                                  __half* __restrict__ cast_dst) {
    constexpr int KD = DDIM, ND = FDIM, NC = KD / 64;
    int tid = threadIdx.x;

    if (blockIdx.y == (FDIM / 128)) {
        int bid = blockIdx.x * 8 + blockIdx.z;          // 0..511
        const int chunk = CAST_N4 / 512;
        int base = bid * chunk;
#pragma unroll 4
        for (int i = base + tid; i < base + chunk; i += 256)
            cast4(cast_src, cast_dst, i);
        return;
    }

    int e = blockIdx.z;
    int cnt = g_cnt[e];
    int m0 = blockIdx.x * 128;
    if (m0 >= cnt) return;
    int n0 = blockIdx.y * 128;

    const __half* Be = Wh + (size_t)e * ((size_t)KD * ND);

    extern __shared__ char smem[];
    uint32_t sb = (smem_to_u32(smem) + 127u) & ~127u;
    uint32_t mb = sb + MB_OFF;

    int lane = tid & 31, warp = tid >> 5;
    int wm = warp >> 2, wn = warp & 3;
    int gid = lane >> 2, tig = lane & 3;

    if (tid == 0) {
#pragma unroll
        for (int s = 0; s < 3; s++) {
            MBARRIER_INIT(mb + s * 16, 256);
            MBARRIER_INIT(mb + s * 16 + 8, 256);
        }
    }
    __syncthreads();

    // ---- staging (8 chunks of 16B per thread) ----
    int rA = tid >> 2, sA = tid & 3;
    int r0 = m0 + rA, r1 = r0 + 64;
    int t0 = (r0 < cnt) ? g_tok[e * 8192 + r0] : 0;
    int t1 = (r1 < cnt) ? g_tok[e * 8192 + r1] : 0;
    const __half* srcA0 = g_xh + (size_t)t0 * KD + sA * 8;
    const __half* srcA1 = g_xh + (size_t)t1 * KD + sA * 8;
    uint32_t dA00 = (uint32_t)(rA * 128 + (((sA) ^ (rA & 7)) << 4));
    uint32_t dA01 = (uint32_t)(rA * 128 + (((sA + 4) ^ (rA & 7)) << 4));
    uint32_t dA10 = dA00 + 64 * 128;
    uint32_t dA11 = dA01 + 64 * 128;
    int kB = tid >> 4, sB = tid & 15;
    const __half* srcB0 = Be + (size_t)kB * ND + n0 + sB * 8;
    uint32_t dB0 = (uint32_t)(B_OFF + kB * 256 + ((sB ^ (kB & 7)) << 4));

    // ---- ldmatrix addresses ----
    uint32_t addrA[4];
    {
        int grp = lane >> 3;
        int rlo = (lane & 7) + ((grp & 1) << 3);
        int segb = grp >> 1;
#pragma unroll
        for (int mi = 0; mi < 4; mi++) {
            int row = wm * 64 + mi * 16 + rlo;
            int p = (segb ^ (row & 7)) & 7;
            addrA[mi] = (uint32_t)(row * 128 + (p << 4));
        }
    }
    uint32_t addrB[2];
    {
        int grp = lane >> 3;
        int krow = ((grp & 1) << 3) + (lane & 7);
#pragma unroll
        for (int pr = 0; pr < 2; pr++) {
            int s = wn * 4 + pr * 2 + (grp >> 1);
            int p = s ^ (krow & 7);
            addrB[pr] = (uint32_t)(B_OFF + krow * 256 + (p << 4));
        }
    }

    float acc[4][4][4];
#pragma unroll
    for (int mi = 0; mi < 4; mi++)
#pragma unroll
        for (int ni = 0; ni < 4; ni++)
#pragma unroll
            for (int q = 0; q < 4; q++) acc[mi][ni][q] = 0.f;

    auto issue = [&](int slot, int kt) {
        uint32_t st = sb + (uint32_t)slot * STAGE_BYTES;
        cp16(st + dA00, srcA0 + kt);
        cp16(st + dA01, srcA0 + kt + 32);
        cp16(st + dA10, srcA1 + kt);
        cp16(st + dA11, srcA1 + kt + 32);
        const __half* bs = srcB0 + (size_t)kt * ND;
#pragma unroll
        for (int j = 0; j < 4; j++)
            cp16(st + dB0 + (uint32_t)j * 4096, bs + (size_t)(16 * j) * ND);
    };

    int pst = 0, pph = 1, cst = 0, cph = 0;
#pragma unroll
    for (int s = 0; s < 2; s++) {
        MBARRIER_WAIT_PARITY(mb + pst * 16 + 8, pph);
        issue(pst, s * 64);
        CP_MBAR_ARRIVE(mb + pst * 16);
        if (++pst == 3) { pst = 0; pph ^= 1; }
    }

#pragma unroll 1
    for (int c = 0; c < NC; c++) {
        if (c + 2 < NC) {
            MBARRIER_WAIT_PARITY(mb + pst * 16 + 8, pph);
            issue(pst, (c + 2) * 64);
            CP_MBAR_ARRIVE(mb + pst * 16);
            if (++pst == 3) { pst = 0; pph ^= 1; }
        }
        MBARRIER_WAIT_PARITY(mb + cst * 16, cph);
        uint32_t st = sb + (uint32_t)cst * STAGE_BYTES;
#pragma unroll
        for (int ks = 0; ks < 4; ks++) {
            uint32_t a[4][4], b[4][2];
#pragma unroll
            for (int mi = 0; mi < 4; mi++)
                ldsm4(a[mi], st + (addrA[mi] ^ ((uint32_t)ks << 5)));
#pragma unroll
            for (int pr = 0; pr < 2; pr++) {
                uint32_t t4[4];
                ldsm4t(t4, st + addrB[pr] + (uint32_t)ks * 4096);
                b[2 * pr][0] = t4[0]; b[2 * pr][1] = t4[1];
                b[2 * pr + 1][0] = t4[2]; b[2 * pr + 1][1] = t4[3];
            }
#pragma unroll
            for (int mi = 0; mi < 4; mi++)
#pragma unroll
                for (int ni = 0; ni < 4; ni++)
                    mma16(acc[mi][ni], a[mi], b[ni]);
        }
        MBARRIER_ARRIVE(mb + cst * 16 + 8);
        if (++cst == 3) { cst = 0; cph ^= 1; }
    }

    // ---- epilogue: bias + silu (HW tanh) -> fp16 g_h ----
    const float* bptr = bias + (size_t)e * ND;
#pragma unroll
    for (int mi = 0; mi < 4; mi++) {
        int gr0 = m0 + wm * 64 + mi * 16 + gid;
        int gr1 = gr0 + 8;
        bool v0 = gr0 < cnt, v1 = gr1 < cnt;
#pragma unroll
        for (int ni = 0; ni < 4; ni++) {
            int gc = n0 + wn * 32 + ni * 8 + tig * 2;
            float bb0 = bptr[gc], bb1 = bptr[gc + 1];
            float p0x = silu_f(acc[mi][ni][0] + bb0);
            float p0y = silu_f(acc[mi][ni][1] + bb1);
            float p1x = silu_f(acc[mi][ni][2] + bb0);
            float p1y = silu_f(acc[mi][ni][3] + bb1);
            __half* h0 = g_h + (size_t)(e * 8192 + gr0) * ND + gc;
            __half* h1 = g_h + (size_t)(e * 8192 + gr1) * ND + gc;
            if (v0) *(__half2*)h0 = __floats2half2_rn(p0x, p0y);
            if (v1) *(__half2*)h1 = __floats2half2_rn(p1x, p1y);
        }
    }
}

// ---------------- GEMM2: writes raw y to g_y --------------------------------
__global__ __launch_bounds__(256, 2) void k_gemm2(const __half* __restrict__ Wh) {
    constexpr int KD = FDIM, ND = DDIM, NC = KD / 64;
    int tid = threadIdx.x;

    int e = blockIdx.z;
    int cnt = g_cnt[e];
    int m0 = blockIdx.x * 128;
    if (m0 >= cnt) return;
    int n0 = blockIdx.y * 128;

    const __half* Be = Wh + (size_t)e * ((size_t)KD * ND);

    extern __shared__ char smem[];
    uint32_t sb = (smem_to_u32(smem) + 127u) & ~127u;
    uint32_t mb = sb + MB_OFF;

    int lane = tid & 31, warp = tid >> 5;
    int wm = warp >> 2, wn = warp & 3;
    int gid = lane >> 2, tig = lane & 3;

    if (tid == 0) {
#pragma unroll
        for (int s = 0; s < 3; s++) {
            MBARRIER_INIT(mb + s * 16, 256);
            MBARRIER_INIT(mb + s * 16 + 8, 256);
        }
    }
    __syncthreads();

    // ---- staging (8 chunks of 16B per thread) ----
    int rA = tid >> 2, sA = tid & 3;
    const __half* srcA0 = g_h + (size_t)(e * 8192 + m0 + rA) * KD + sA * 8;
    const __half* srcA1 = srcA0 + (size_t)64 * KD;
    uint32_t dA00 = (uint32_t)(rA * 128 + (((sA) ^ (rA & 7)) << 4));
    uint32_t dA01 = (uint32_t)(rA * 128 + (((sA + 4) ^ (rA & 7)) << 4));
    uint32_t dA10 = dA00 + 64 * 128;
    uint32_t dA11 = dA01 + 64 * 128;
    int kB = tid >> 4, sB = tid & 15;
    const __half* srcB0 = Be + (size_t)kB * ND + n0 + sB * 8;
    uint32_t dB0 = (uint32_t)(B_OFF + kB * 256 + ((sB ^ (kB & 7)) << 4));

    // ---- ldmatrix addresses ----
    uint32_t addrA[4];
    {
        int grp = lane >> 3;
        int rlo = (lane & 7) + ((grp & 1) << 3);
        int segb = grp >> 1;
#pragma unroll
        for (int mi = 0; mi < 4; mi++) {
            int row = wm * 64 + mi * 16 + rlo;
            int p = (segb ^ (row & 7)) & 7;
            addrA[mi] = (uint32_t)(row * 128 + (p << 4));
        }
    }
    uint32_t addrB[2];
    {
        int grp = lane >> 3;
        int krow = ((grp & 1) << 3) + (lane & 7);
#pragma unroll
        for (int pr = 0; pr < 2; pr++) {
            int s = wn * 4 + pr * 2 + (grp >> 1);
            int p = s ^ (krow & 7);
            addrB[pr] = (uint32_t)(B_OFF + krow * 256 + (p << 4));
        }
    }

    float acc[4][4][4];
#pragma unroll
    for (int mi = 0; mi < 4; mi++)
#pragma unroll
        for (int ni = 0; ni < 4; ni++)
#pragma unroll
            for (int q = 0; q < 4; q++) acc[mi][ni][q] = 0.f;

    auto issue = [&](int slot, int kt) {
        uint32_t st = sb + (uint32_t)slot * STAGE_BYTES;
        cp16(st + dA00, srcA0 + kt);
        cp16(st + dA01, srcA0 + kt + 32);
        cp16(st + dA10, srcA1 + kt);
        cp16(st + dA11, srcA1 + kt + 32);
        const __half* bs = srcB0 + (size_t)kt * ND;
#pragma unroll
        for (int j = 0; j < 4; j++)
            cp16(st + dB0 + (uint32_t)j * 4096, bs + (size_t)(16 * j) * ND);
    };

    int pst = 0, pph = 1, cst = 0, cph = 0;
#pragma unroll
    for (int s = 0; s < 2; s++) {
        MBARRIER_WAIT_PARITY(mb + pst * 16 + 8, pph);
        issue(pst, s * 64);
        CP_MBAR_ARRIVE(mb + pst * 16);
        if (++pst == 3) { pst = 0; pph ^= 1; }
    }

#pragma unroll 1
    for (int c = 0; c < NC; c++) {
        if (c + 2 < NC) {
            MBARRIER_WAIT_PARITY(mb + pst * 16 + 8, pph);
            issue(pst, (c + 2) * 64);
            CP_MBAR_ARRIVE(mb + pst * 16);
            if (++pst == 3) { pst = 0; pph ^= 1; }
        }
        MBARRIER_WAIT_PARITY(mb + cst * 16, cph);
        uint32_t st = sb + (uint32_t)cst * STAGE_BYTES;
#pragma unroll
        for (int ks = 0; ks < 4; ks++) {
            uint32_t a[4][4], b[4][2];
#pragma unroll
            for (int mi = 0; mi < 4; mi++)
                ldsm4(a[mi], st + (addrA[mi] ^ ((uint32_t)ks << 5)));
#pragma unroll
            for (int pr = 0; pr < 2; pr++) {
                uint32_t t4[4];
                ldsm4t(t4, st + addrB[pr] + (uint32_t)ks * 4096);
                b[2 * pr][0] = t4[0]; b[2 * pr][1] = t4[1];
                b[2 * pr + 1][0] = t4[2]; b[2 * pr + 1][1] = t4[3];
            }
#pragma unroll
            for (int mi = 0; mi < 4; mi++)
#pragma unroll
                for (int ni = 0; ni < 4; ni++)
                    mma16(acc[mi][ni], a[mi], b[ni]);
        }
        MBARRIER_ARRIVE(mb + cst * 16 + 8);
        if (++cst == 3) { cst = 0; cph ^= 1; }
    }

    // ---- epilogue: raw y (bias + weight applied in combine) ----
#pragma unroll
    for (int mi = 0; mi < 4; mi++) {
        int gr0 = m0 + wm * 64 + mi * 16 + gid;
        int gr1 = gr0 + 8;
        bool v0 = gr0 < cnt, v1 = gr1 < cnt;
        float* o0 = g_y + (size_t)(e * 8192 + gr0) * ND;
        float* o1 = g_y + (size_t)(e * 8192 + gr1) * ND;
#pragma unroll
        for (int ni = 0; ni < 4; ni++) {
            int gc = n0 + wn * 32 + ni * 8 + tig * 2;
            if (v0) *(float2*)(o0 + gc) = make_float2(acc[mi][ni][0], acc[mi][ni][1]);
            if (v1) *(float2*)(o1 + gc) = make_float2(acc[mi][ni][2], acc[mi][ni][3]);
        }
    }
}

// ---------------- combine ----------------
__global__ void k_combine(float* __restrict__ out, const float* __restrict__ b2) {
    int t = blockIdx.x;
    int s0 = g_slot[t * 2 + 0], s1 = g_slot[t * 2 + 1];
    float w0 = g_w[s0], w1 = g_w[s1];
    int e0 = s0 >> 13, e1 = s1 >> 13;
    const float4* y0 = (const float4*)(g_y + (size_t)s0 * DDIM);
    const float4* y1 = (const float4*)(g_y + (size_t)s1 * DDIM);
    const float4* b20 = (const float4*)(b2 + (size_t)e0 * DDIM);
    const float4* b21 = (const float4*)(b2 + (size_t)e1 * DDIM);
    float4* o = (float4*)(out + (size_t)t * DDIM);
    int i = threadIdx.x;
    float4 a = y0[i], b = y1[i], c0 = b20[i], c1 = b21[i];
    float4 r;
    r.x = w0 * (a.x + c0.x) + w1 * (b.x + c1.x);
    r.y = w0 * (a.y + c0.y) + w1 * (b.y + c1.y);
    r.z = w0 * (a.z + c0.z) + w1 * (b.z + c1.z);
    r.w = w0 * (a.w + c0.w) + w1 * (b.w + c1.w);
    o[i] = r;
}

// ---------------- launch ----------------
extern "C" void kernel_launch(void* const* d_in, const int* in_sizes, int n_in,
                              void* d_out, int out_size) {
    const float* inputs  = (const float*)d_in[0];
    const float* task    = (const float*)d_in[1];
    const float* Wg_in   = (const float*)d_in[2];
    const float* bg_in   = (const float*)d_in[3];
    const float* Wg_task = (const float*)d_in[4];
    const float* bg_task = (const float*)d_in[5];
    const float* alpha   = (const float*)d_in[6];
    const float* W1      = (const float*)d_in[7];
    const float* b1      = (const float*)d_in[8];
    const float* W2      = (const float*)d_in[9];
    const float* b2      = (const float*)d_in[10];
    float* out = (float*)d_out;

    cudaFuncSetAttribute(k_gemm1, cudaFuncAttributeMaxDynamicSharedMemorySize, SMEM_DYN);
    cudaFuncSetAttribute(k_gemm2, cudaFuncAttributeMaxDynamicSharedMemorySize, SMEM_DYN);

    __half* w1h_p; cudaGetSymbolAddress((void**)&w1h_p, g_w1h);
    __half* w2h_p; cudaGetSymbolAddress((void**)&w2h_p, g_w2h);

    k_init<<<1, 32>>>();
    // gate (1024) + W1 cast (32768) in one launch
    k_pregate<<<1024 + 32768, 256>>>(inputs, Wg_in, bg_in, alpha,
                                     task, Wg_task, bg_task, W1, w1h_p);
    k_laux<<<1, 256>>>(out, out_size);
    // GEMM1 (chunk-64, 3-stage, tanh-silu) + W2-cast rider (blockIdx.y == 32)
    k_gemm1<<<dim3(64, FDIM / 128 + 1, NEXP), 256, SMEM_DYN>>>(w1h_p, b1, W2, w2h_p);
    // GEMM2 (chunk-64, 3-stage) -> g_y
    k_gemm2<<<dim3(64, DDIM / 128, NEXP), 256, SMEM_DYN>>>(w2h_p);
    k_combine<<<TOK, 256>>>(out, b2);
}

// round 16
// speedup vs baseline: 1.0522x; 1.0181x over previous
#include <cuda_runtime.h>
#include <cuda_fp16.h>
#include <cstdint>

#define TOK   8192
#define DDIM  1024
#define FDIM  4096
#define NEXP  8
#define CAST_N4 (NEXP * DDIM * FDIM / 4)   // 8.39M float4 per weight tensor

// ---------------- device scratch ----------------
__device__ __half g_xh[(size_t)TOK * DDIM];             // fp16 inputs
__device__ __half g_h[(size_t)NEXP * 8192 * FDIM];      // fp16 silu(x@W1+b1)
__device__ float  g_y[(size_t)NEXP * 8192 * DDIM];      // raw expert output (fp32)
__device__ __half g_w1h[(size_t)NEXP * DDIM * FDIM];    // W1 fp16, [K][N] layout
__device__ __half g_w2h[(size_t)NEXP * DDIM * FDIM];    // W2 fp16, [K][N] layout
__device__ int    g_tok[NEXP * 8192];
__device__ float  g_w[NEXP * 8192];
__device__ int    g_slot[TOK * 2];
__device__ float  g_partial[1024 * NEXP];
__device__ int    g_cnt[NEXP];   // zero at load; reset by combine rider each call

// ---------------- helpers ----------------
__device__ __forceinline__ uint32_t smem_to_u32(const void* p) {
    uint32_t a;
    asm("{ .reg .u64 t; cvta.to.shared.u64 t, %1; cvt.u32.u64 %0, t; }" : "=r"(a) : "l"(p));
    return a;
}
__device__ __forceinline__ void cp16(uint32_t dst, const void* src) {
    asm volatile("cp.async.cg.shared.global [%0], [%1], 16;" :: "r"(dst), "l"(src));
}
// arrive on mbarrier when this thread's prior cp.asyncs complete (.noinc: counts
// against the init count — one tracked arrive per thread).
#define CP_MBAR_ARRIVE(mbar) \
    asm volatile("cp.async.mbarrier.arrive.noinc.shared.b64 [%0];" :: "r"((uint32_t)(mbar)) : "memory")

#define MBARRIER_INIT(mbar, count) \
    asm volatile("mbarrier.init.shared.b64 [%0], %1;" \
        :: "r"((uint32_t)(mbar)), "r"((uint32_t)(count)) : "memory")
#define MBARRIER_ARRIVE(mbar) \
    asm volatile("mbarrier.arrive.shared.b64 _, [%0];" :: "r"((uint32_t)(mbar)) : "memory")

#define MBARRIER_WAIT_PARITY(mbar_smem_addr, phase_parity) do { \
    uint32_t _mbar = (uint32_t)(mbar_smem_addr); \
    uint32_t _parity = (uint32_t)(phase_parity); \
    uint32_t _done; \
    asm volatile("{\n\t.reg .pred p;\n\t" \
        "mbarrier.try_wait.parity.acquire.cta.shared::cta.b64 p, [%1], %2;\n\t" \
        "selp.b32 %0, 1, 0, p;\n\t}" \
        : "=r"(_done) : "r"(_mbar), "r"(_parity) : "memory"); \
    if (!_done) { \
        asm volatile("{\n\t.reg .pred P1;\n\t" \
            "WAIT_LOOP_%=:\n\t" \
            "mbarrier.try_wait.parity.acquire.cta.shared::cta.b64 P1, [%0], %1, 0x989680;\n\t" \
            "@P1 bra.uni WAIT_DONE_%=;\n\t" \
            "bra.uni WAIT_LOOP_%=;\n\t" \
            "WAIT_DONE_%=:\n\t}" \
            :: "r"(_mbar), "r"(_parity) : "memory"); \
    } \
} while(0)

__device__ __forceinline__ void ldsm4(uint32_t* r, uint32_t addr) {
    asm volatile("ldmatrix.sync.aligned.m8n8.x4.shared.b16 {%0,%1,%2,%3}, [%4];"
                 : "=r"(r[0]), "=r"(r[1]), "=r"(r[2]), "=r"(r[3]) : "r"(addr));
}
__device__ __forceinline__ void ldsm4t(uint32_t* r, uint32_t addr) {
    asm volatile("ldmatrix.sync.aligned.m8n8.x4.trans.shared.b16 {%0,%1,%2,%3}, [%4];"
                 : "=r"(r[0]), "=r"(r[1]), "=r"(r[2]), "=r"(r[3]) : "r"(addr));
}
// fp16 MMA, fp32 accumulate: D(16x8) += A(16x16) * B(16x8)
__device__ __forceinline__ void mma16(float* d, const uint32_t* a, const uint32_t* b) {
    asm("mma.sync.aligned.m16n8k16.row.col.f32.f16.f16.f32 "
        "{%0,%1,%2,%3}, {%4,%5,%6,%7}, {%8,%9}, {%0,%1,%2,%3};"
        : "+f"(d[0]), "+f"(d[1]), "+f"(d[2]), "+f"(d[3])
        : "r"(a[0]), "r"(a[1]), "r"(a[2]), "r"(a[3]), "r"(b[0]), "r"(b[1]));
}

__device__ __forceinline__ void cast4(const float* __restrict__ src,
                                      __half* __restrict__ dst, int i) {
    float4 v = ((const float4*)src)[i];
    __half2 h0 = __floats2half2_rn(v.x, v.y);
    __half2 h1 = __floats2half2_rn(v.z, v.w);
    uint2 u;
    u.x = *(uint32_t*)&h0;
    u.y = *(uint32_t*)&h1;
    ((uint2*)dst)[i] = u;
}

// silu via single-instruction HW tanh: x * 0.5 * (1 + tanh(x/2))
__device__ __forceinline__ float silu_f(float x) {
    float t;
    asm("tanh.approx.f32 %0, %1;" : "=f"(t) : "f"(x * 0.5f));
    return x * 0.5f * (1.f + t);
}

// ---------------- pre-kernel: gate + W1 cast ----------------
// blocks [0,1024) = gating (task-gate inline); blocks [1024,1024+32768) = W1 cast.
__global__ void k_pregate(const float* __restrict__ x,
                          const float* __restrict__ Wg,
                          const float* __restrict__ bg,
                          const float* __restrict__ alpha_p,
                          const float* __restrict__ task,
                          const float* __restrict__ Wgt,
                          const float* __restrict__ bgt,
                          const float* __restrict__ W1,
                          __half* __restrict__ w1h) {
    if (blockIdx.x >= 1024) {
        int i = (blockIdx.x - 1024) * 256 + threadIdx.x;
        if (i < CAST_N4) cast4(W1, w1h, i);
        return;
    }

    // ---- inline task gate ----
    __shared__ float red[256][8];
    __shared__ float tg[8];
    {
        float p[8];
#pragma unroll
        for (int e = 0; e < 8; e++) p[e] = 0.f;
        for (int d = threadIdx.x; d < DDIM; d += 256) {
            float tv = task[d];
#pragma unroll
            for (int e = 0; e < 8; e++) p[e] += tv * Wgt[d * 8 + e];
        }
#pragma unroll
        for (int e = 0; e < 8; e++) red[threadIdx.x][e] = p[e];
        __syncthreads();
        if (threadIdx.x < 8) {
            float s = bgt[threadIdx.x];
            for (int w = 0; w < 256; w++) s += red[w][threadIdx.x];
            tg[threadIdx.x] = s;
        }
        __syncthreads();
    }

    // ---- per-token gating: one warp per token ----
    int warp = threadIdx.x >> 5, lane = threadIdx.x & 31;
    int t = blockIdx.x * 8 + warp;
    const float* xr = x + (size_t)t * DDIM;
    __half* xw = g_xh + (size_t)t * DDIM;

    float acc[8];
#pragma unroll
    for (int e = 0; e < 8; e++) acc[e] = 0.f;
#pragma unroll 4
    for (int i = 0; i < 32; i++) {
        int d = i * 32 + lane;
        float xv = xr[d];
        xw[d] = __float2half_rn(xv);
#pragma unroll
        for (int e = 0; e < 8; e++) acc[e] += xv * Wg[d * 8 + e];
    }
#pragma unroll
    for (int off = 16; off > 0; off >>= 1)
#pragma unroll
        for (int e = 0; e < 8; e++)
            acc[e] += __shfl_xor_sync(0xffffffffu, acc[e], off);

    float alpha = alpha_p[0];
    float logits[8];
#pragma unroll
    for (int e = 0; e < 8; e++) {
        float v = (1.f - alpha) * (acc[e] + bg[e]) + alpha * tg[e];
        if (!isfinite(v)) v = 0.f;
        logits[e] = v;
    }

    float m = logits[0];
#pragma unroll
    for (int e = 1; e < 8; e++) m = fmaxf(m, logits[e]);
    float ssum = 0.f, sm[8];
#pragma unroll
    for (int e = 0; e < 8; e++) { sm[e] = expf(logits[e] - m); ssum += sm[e]; }
    float inv = 1.f / ssum;
#pragma unroll
    for (int e = 0; e < 8; e++) sm[e] *= inv;

    __shared__ float wsm[8][8];
#pragma unroll
    for (int e = 0; e < 8; e++) if (lane == e) wsm[warp][e] = sm[e];
    __syncthreads();
    if (threadIdx.x < 8) {
        float s2 = 0.f;
#pragma unroll
        for (int w = 0; w < 8; w++) s2 += wsm[w][threadIdx.x];
        g_partial[blockIdx.x * 8 + threadIdx.x] = s2;
    }

    float v0 = -1e30f; int i0 = 0;
#pragma unroll
    for (int e = 0; e < 8; e++) if (logits[e] > v0) { v0 = logits[e]; i0 = e; }
    float v1 = -1e30f; int i1 = 0;
#pragma unroll
    for (int e = 0; e < 8; e++) if (e != i0 && logits[e] > v1) { v1 = logits[e]; i1 = e; }

    float ew = expf(v1 - v0);
    float w0 = 1.f / (1.f + ew);
    float w1 = ew / (1.f + ew);

    if (lane == 0) {
        int p0 = atomicAdd(&g_cnt[i0], 1);
        int s0 = i0 * 8192 + p0;
        g_tok[s0] = t; g_w[s0] = w0; g_slot[t * 2 + 0] = s0;
        int p1 = atomicAdd(&g_cnt[i1], 1);
        int s1 = i1 * 8192 + p1;
        g_tok[s1] = t; g_w[s1] = w1; g_slot[t * 2 + 1] = s1;
    }
}

// ---------------- GEMM common shape: 128x128xK64, 3-stage mbarrier pipeline ----
#define STAGE_BYTES 32768
#define B_OFF 16384
#define MB_OFF (3 * STAGE_BYTES)
#define SMEM_DYN (3 * STAGE_BYTES + 128)

// ---------------- GEMM1 (+ W2-cast rider on blockIdx.y == FDIM/128) ----------
__global__ __launch_bounds__(256, 2) void k_gemm1(const __half* __restrict__ Wh,
                                                  const float* __restrict__ bias,
                                                  const float* __restrict__ cast_src,
                                                  __half* __restrict__ cast_dst) {
    constexpr int KD = DDIM, ND = FDIM, NC = KD / 64;
    int tid = threadIdx.x;

    if (blockIdx.y == (FDIM / 128)) {
        int bid = blockIdx.x * 8 + blockIdx.z;          // 0..511
        const int chunk = CAST_N4 / 512;
        int base = bid * chunk;
#pragma unroll 4
        for (int i = base + tid; i < base + chunk; i += 256)
            cast4(cast_src, cast_dst, i);
        return;
    }

    int e = blockIdx.z;
    int cnt = g_cnt[e];
    int m0 = blockIdx.x * 128;
    if (m0 >= cnt) return;
    int n0 = blockIdx.y * 128;

    const __half* Be = Wh + (size_t)e * ((size_t)KD * ND);

    extern __shared__ char smem[];
    uint32_t sb = (smem_to_u32(smem) + 127u) & ~127u;
    uint32_t mb = sb + MB_OFF;

    int lane = tid & 31, warp = tid >> 5;
    int wm = warp >> 2, wn = warp & 3;
    int gid = lane >> 2, tig = lane & 3;

    if (tid == 0) {
#pragma unroll
        for (int s = 0; s < 3; s++) {
            MBARRIER_INIT(mb + s * 16, 256);
            MBARRIER_INIT(mb + s * 16 + 8, 256);
        }
    }
    __syncthreads();

    // ---- staging (8 chunks of 16B per thread) ----
    int rA = tid >> 2, sA = tid & 3;
    int r0 = m0 + rA, r1 = r0 + 64;
    int t0 = (r0 < cnt) ? g_tok[e * 8192 + r0] : 0;
    int t1 = (r1 < cnt) ? g_tok[e * 8192 + r1] : 0;
    const __half* srcA0 = g_xh + (size_t)t0 * KD + sA * 8;
    const __half* srcA1 = g_xh + (size_t)t1 * KD + sA * 8;
    uint32_t dA00 = (uint32_t)(rA * 128 + (((sA) ^ (rA & 7)) << 4));
    uint32_t dA01 = (uint32_t)(rA * 128 + (((sA + 4) ^ (rA & 7)) << 4));
    uint32_t dA10 = dA00 + 64 * 128;
    uint32_t dA11 = dA01 + 64 * 128;
    int kB = tid >> 4, sB = tid & 15;
    const __half* srcB0 = Be + (size_t)kB * ND + n0 + sB * 8;
    uint32_t dB0 = (uint32_t)(B_OFF + kB * 256 + ((sB ^ (kB & 7)) << 4));

    // ---- ldmatrix addresses ----
    uint32_t addrA[4];
    {
        int grp = lane >> 3;
        int rlo = (lane & 7) + ((grp & 1) << 3);
        int segb = grp >> 1;
#pragma unroll
        for (int mi = 0; mi < 4; mi++) {
            int row = wm * 64 + mi * 16 + rlo;
            int p = (segb ^ (row & 7)) & 7;
            addrA[mi] = (uint32_t)(row * 128 + (p << 4));
        }
    }
    uint32_t addrB[2];
    {
        int grp = lane >> 3;
        int krow = ((grp & 1) << 3) + (lane & 7);
#pragma unroll
        for (int pr = 0; pr < 2; pr++) {
            int s = wn * 4 + pr * 2 + (grp >> 1);
            int p = s ^ (krow & 7);
            addrB[pr] = (uint32_t)(B_OFF + krow * 256 + (p << 4));
        }
    }

    float acc[4][4][4];
#pragma unroll
    for (int mi = 0; mi < 4; mi++)
#pragma unroll
        for (int ni = 0; ni < 4; ni++)
#pragma unroll
            for (int q = 0; q < 4; q++) acc[mi][ni][q] = 0.f;

    auto issue = [&](int slot, int kt) {
        uint32_t st = sb + (uint32_t)slot * STAGE_BYTES;
        cp16(st + dA00, srcA0 + kt);
        cp16(st + dA01, srcA0 + kt + 32);
        cp16(st + dA10, srcA1 + kt);
        cp16(st + dA11, srcA1 + kt + 32);
        const __half* bs = srcB0 + (size_t)kt * ND;
#pragma unroll
        for (int j = 0; j < 4; j++)
            cp16(st + dB0 + (uint32_t)j * 4096, bs + (size_t)(16 * j) * ND);
    };

    int pst = 0, pph = 1, cst = 0, cph = 0;
#pragma unroll
    for (int s = 0; s < 2; s++) {
        MBARRIER_WAIT_PARITY(mb + pst * 16 + 8, pph);
        issue(pst, s * 64);
        CP_MBAR_ARRIVE(mb + pst * 16);
        if (++pst == 3) { pst = 0; pph ^= 1; }
    }

#pragma unroll 1
    for (int c = 0; c < NC; c++) {
        if (c + 2 < NC) {
            MBARRIER_WAIT_PARITY(mb + pst * 16 + 8, pph);
            issue(pst, (c + 2) * 64);
            CP_MBAR_ARRIVE(mb + pst * 16);
            if (++pst == 3) { pst = 0; pph ^= 1; }
        }
        MBARRIER_WAIT_PARITY(mb + cst * 16, cph);
        uint32_t st = sb + (uint32_t)cst * STAGE_BYTES;
#pragma unroll
        for (int ks = 0; ks < 4; ks++) {
            uint32_t a[4][4], b[4][2];
#pragma unroll
            for (int mi = 0; mi < 4; mi++)
                ldsm4(a[mi], st + (addrA[mi] ^ ((uint32_t)ks << 5)));
#pragma unroll
            for (int pr = 0; pr < 2; pr++) {
                uint32_t t4[4];
                ldsm4t(t4, st + addrB[pr] + (uint32_t)ks * 4096);
                b[2 * pr][0] = t4[0]; b[2 * pr][1] = t4[1];
                b[2 * pr + 1][0] = t4[2]; b[2 * pr + 1][1] = t4[3];
            }
#pragma unroll
            for (int mi = 0; mi < 4; mi++)
#pragma unroll
                for (int ni = 0; ni < 4; ni++)
                    mma16(acc[mi][ni], a[mi], b[ni]);
        }
        MBARRIER_ARRIVE(mb + cst * 16 + 8);
        if (++cst == 3) { cst = 0; cph ^= 1; }
    }

    // ---- epilogue: bias + silu (HW tanh) -> fp16 g_h ----
    const float* bptr = bias + (size_t)e * ND;
#pragma unroll
    for (int mi = 0; mi < 4; mi++) {
        int gr0 = m0 + wm * 64 + mi * 16 + gid;
        int gr1 = gr0 + 8;
        bool v0 = gr0 < cnt, v1 = gr1 < cnt;
#pragma unroll
        for (int ni = 0; ni < 4; ni++) {
            int gc = n0 + wn * 32 + ni * 8 + tig * 2;
            float bb0 = bptr[gc], bb1 = bptr[gc + 1];
            float p0x = silu_f(acc[mi][ni][0] + bb0);
            float p0y = silu_f(acc[mi][ni][1] + bb1);
            float p1x = silu_f(acc[mi][ni][2] + bb0);
            float p1y = silu_f(acc[mi][ni][3] + bb1);
            __half* h0 = g_h + (size_t)(e * 8192 + gr0) * ND + gc;
            __half* h1 = g_h + (size_t)(e * 8192 + gr1) * ND + gc;
            if (v0) *(__half2*)h0 = __floats2half2_rn(p0x, p0y);
            if (v1) *(__half2*)h1 = __floats2half2_rn(p1x, p1y);
        }
    }
}

// ---------------- GEMM2: writes raw y to g_y --------------------------------
__global__ __launch_bounds__(256, 2) void k_gemm2(const __half* __restrict__ Wh) {
    constexpr int KD = FDIM, ND = DDIM, NC = KD / 64;
    int tid = threadIdx.x;

    int e = blockIdx.z;
    int cnt = g_cnt[e];
    int m0 = blockIdx.x * 128;
    if (m0 >= cnt) return;
    int n0 = blockIdx.y * 128;

    const __half* Be = Wh + (size_t)e * ((size_t)KD * ND);

    extern __shared__ char smem[];
    uint32_t sb = (smem_to_u32(smem) + 127u) & ~127u;
    uint32_t mb = sb + MB_OFF;

    int lane = tid & 31, warp = tid >> 5;
    int wm = warp >> 2, wn = warp & 3;
    int gid = lane >> 2, tig = lane & 3;

    if (tid == 0) {
#pragma unroll
        for (int s = 0; s < 3; s++) {
            MBARRIER_INIT(mb + s * 16, 256);
            MBARRIER_INIT(mb + s * 16 + 8, 256);
        }
    }
    __syncthreads();

    // ---- staging (8 chunks of 16B per thread) ----
    int rA = tid >> 2, sA = tid & 3;
    const __half* srcA0 = g_h + (size_t)(e * 8192 + m0 + rA) * KD + sA * 8;
    const __half* srcA1 = srcA0 + (size_t)64 * KD;
    uint32_t dA00 = (uint32_t)(rA * 128 + (((sA) ^ (rA & 7)) << 4));
    uint32_t dA01 = (uint32_t)(rA * 128 + (((sA + 4) ^ (rA & 7)) << 4));
    uint32_t dA10 = dA00 + 64 * 128;
    uint32_t dA11 = dA01 + 64 * 128;
    int kB = tid >> 4, sB = tid & 15;
    const __half* srcB0 = Be + (size_t)kB * ND + n0 + sB * 8;
    uint32_t dB0 = (uint32_t)(B_OFF + kB * 256 + ((sB ^ (kB & 7)) << 4));

    // ---- ldmatrix addresses ----
    uint32_t addrA[4];
    {
        int grp = lane >> 3;
        int rlo = (lane & 7) + ((grp & 1) << 3);
        int segb = grp >> 1;
#pragma unroll
        for (int mi = 0; mi < 4; mi++) {
            int row = wm * 64 + mi * 16 + rlo;
            int p = (segb ^ (row & 7)) & 7;
            addrA[mi] = (uint32_t)(row * 128 + (p << 4));
        }
    }
    uint32_t addrB[2];
    {
        int grp = lane >> 3;
        int krow = ((grp & 1) << 3) + (lane & 7);
#pragma unroll
        for (int pr = 0; pr < 2; pr++) {
            int s = wn * 4 + pr * 2 + (grp >> 1);
            int p = s ^ (krow & 7);
            addrB[pr] = (uint32_t)(B_OFF + krow * 256 + (p << 4));
        }
    }

    float acc[4][4][4];
#pragma unroll
    for (int mi = 0; mi < 4; mi++)
#pragma unroll
        for (int ni = 0; ni < 4; ni++)
#pragma unroll
            for (int q = 0; q < 4; q++) acc[mi][ni][q] = 0.f;

    auto issue = [&](int slot, int kt) {
        uint32_t st = sb + (uint32_t)slot * STAGE_BYTES;
        cp16(st + dA00, srcA0 + kt);
        cp16(st + dA01, srcA0 + kt + 32);
        cp16(st + dA10, srcA1 + kt);
        cp16(st + dA11, srcA1 + kt + 32);
        const __half* bs = srcB0 + (size_t)kt * ND;
#pragma unroll
        for (int j = 0; j < 4; j++)
            cp16(st + dB0 + (uint32_t)j * 4096, bs + (size_t)(16 * j) * ND);
    };

    int pst = 0, pph = 1, cst = 0, cph = 0;
#pragma unroll
    for (int s = 0; s < 2; s++) {
        MBARRIER_WAIT_PARITY(mb + pst * 16 + 8, pph);
        issue(pst, s * 64);
        CP_MBAR_ARRIVE(mb + pst * 16);
        if (++pst == 3) { pst = 0; pph ^= 1; }
    }

#pragma unroll 1
    for (int c = 0; c < NC; c++) {
        if (c + 2 < NC) {
            MBARRIER_WAIT_PARITY(mb + pst * 16 + 8, pph);
            issue(pst, (c + 2) * 64);
            CP_MBAR_ARRIVE(mb + pst * 16);
            if (++pst == 3) { pst = 0; pph ^= 1; }
        }
        MBARRIER_WAIT_PARITY(mb + cst * 16, cph);
        uint32_t st = sb + (uint32_t)cst * STAGE_BYTES;
#pragma unroll
        for (int ks = 0; ks < 4; ks++) {
            uint32_t a[4][4], b[4][2];
#pragma unroll
            for (int mi = 0; mi < 4; mi++)
                ldsm4(a[mi], st + (addrA[mi] ^ ((uint32_t)ks << 5)));
#pragma unroll
            for (int pr = 0; pr < 2; pr++) {
                uint32_t t4[4];
                ldsm4t(t4, st + addrB[pr] + (uint32_t)ks * 4096);
                b[2 * pr][0] = t4[0]; b[2 * pr][1] = t4[1];
                b[2 * pr + 1][0] = t4[2]; b[2 * pr + 1][1] = t4[3];
            }
#pragma unroll
            for (int mi = 0; mi < 4; mi++)
#pragma unroll
                for (int ni = 0; ni < 4; ni++)
                    mma16(acc[mi][ni], a[mi], b[ni]);
        }
        MBARRIER_ARRIVE(mb + cst * 16 + 8);
        if (++cst == 3) { cst = 0; cph ^= 1; }
    }

    // ---- epilogue: raw y (bias + weight applied in combine) ----
#pragma unroll
    for (int mi = 0; mi < 4; mi++) {
        int gr0 = m0 + wm * 64 + mi * 16 + gid;
        int gr1 = gr0 + 8;
        bool v0 = gr0 < cnt, v1 = gr1 < cnt;
        float* o0 = g_y + (size_t)(e * 8192 + gr0) * ND;
        float* o1 = g_y + (size_t)(e * 8192 + gr1) * ND;
#pragma unroll
        for (int ni = 0; ni < 4; ni++) {
            int gc = n0 + wn * 32 + ni * 8 + tig * 2;
            if (v0) *(float2*)(o0 + gc) = make_float2(acc[mi][ni][0], acc[mi][ni][1]);
            if (v1) *(float2*)(o1 + gc) = make_float2(acc[mi][ni][2], acc[mi][ni][3]);
        }
    }
}

// ---------------- combine (+ laux rider block that also resets g_cnt) --------
__global__ void k_combine(float* __restrict__ out, const float* __restrict__ b2,
                          int out_size) {
    if (blockIdx.x == TOK) {
        // laux rider: sole reader of g_cnt this kernel; resets it afterwards
        __shared__ float red[256];
        __shared__ float sw[8];
        int tid = threadIdx.x;
        int e = tid & 7, p = tid >> 3;
        float s = 0.f;
        for (int b = p; b < 1024; b += 32) s += g_partial[b * 8 + e];
        red[tid] = s;
        __syncthreads();
        if (tid < 8) {
            float t = 0.f;
            for (int q = 0; q < 32; q++) t += red[(q << 3) | tid];
            sw[tid] = t * (float)g_cnt[tid];
        }
        __syncthreads();
        if (tid == 0) {
            float l = 0.f;
            for (int i = 0; i < 8; i++) l += sw[i];
            out[out_size - 1] = l / (8192.f * 8192.f);
        }
        __syncthreads();
        if (tid < 8) g_cnt[tid] = 0;     // reset for next execution
        return;
    }

    int t = blockIdx.x;
    int s0 = g_slot[t * 2 + 0], s1 = g_slot[t * 2 + 1];
    float w0 = g_w[s0], w1 = g_w[s1];
    int e0 = s0 >> 13, e1 = s1 >> 13;
    const float4* y0 = (const float4*)(g_y + (size_t)s0 * DDIM);
    const float4* y1 = (const float4*)(g_y + (size_t)s1 * DDIM);
    const float4* b20 = (const float4*)(b2 + (size_t)e0 * DDIM);
    const float4* b21 = (const float4*)(b2 + (size_t)e1 * DDIM);
    float4* o = (float4*)(out + (size_t)t * DDIM);
    int i = threadIdx.x;
    float4 a = y0[i], b = y1[i], c0 = b20[i], c1 = b21[i];
    float4 r;
    r.x = w0 * (a.x + c0.x) + w1 * (b.x + c1.x);
    r.y = w0 * (a.y + c0.y) + w1 * (b.y + c1.y);
    r.z = w0 * (a.z + c0.z) + w1 * (b.z + c1.z);
    r.w = w0 * (a.w + c0.w) + w1 * (b.w + c1.w);
    o[i] = r;
}

// ---------------- launch ----------------
extern "C" void kernel_launch(void* const* d_in, const int* in_sizes, int n_in,
                              void* d_out, int out_size) {
    const float* inputs  = (const float*)d_in[0];
    const float* task    = (const float*)d_in[1];
    const float* Wg_in   = (const float*)d_in[2];
    const float* bg_in   = (const float*)d_in[3];
    const float* Wg_task = (const float*)d_in[4];
    const float* bg_task = (const float*)d_in[5];
    const float* alpha   = (const float*)d_in[6];
    const float* W1      = (const float*)d_in[7];
    const float* b1      = (const float*)d_in[8];
    const float* W2      = (const float*)d_in[9];
    const float* b2      = (const float*)d_in[10];
    float* out = (float*)d_out;

    cudaFuncSetAttribute(k_gemm1, cudaFuncAttributeMaxDynamicSharedMemorySize, SMEM_DYN);
    cudaFuncSetAttribute(k_gemm2, cudaFuncAttributeMaxDynamicSharedMemorySize, SMEM_DYN);

    __half* w1h_p; cudaGetSymbolAddress((void**)&w1h_p, g_w1h);
    __half* w2h_p; cudaGetSymbolAddress((void**)&w2h_p, g_w2h);

    // g_cnt is zero at module load and re-zeroed by k_combine's rider block,
    // so every execution (correctness call + each graph replay) starts clean.
    k_pregate<<<1024 + 32768, 256>>>(inputs, Wg_in, bg_in, alpha,
                                     task, Wg_task, bg_task, W1, w1h_p);
    // GEMM1 (chunk-64, 3-stage, tanh-silu) + W2-cast rider (blockIdx.y == 32)
    k_gemm1<<<dim3(64, FDIM / 128 + 1, NEXP), 256, SMEM_DYN>>>(w1h_p, b1, W2, w2h_p);
    // GEMM2 (chunk-64, 3-stage) -> g_y
    k_gemm2<<<dim3(64, DDIM / 128, NEXP), 256, SMEM_DYN>>>(w2h_p);
    // combine + laux rider + g_cnt reset
    k_combine<<<TOK + 1, 256>>>(out, b2, out_size);
}